// round 12
// baseline (speedup 1.0000x reference)
#include <cuda_runtime.h>
#include <cuda_bf16.h>
#include <cstdint>

#define NN 50000
#define NE 600000
#define HD 128

#define EDGE_SMEM 101376   // 25344 u32
#define NODE_SMEM 101376
#define P_SMEM    101376

// interleaved (hi,lo) weight image offsets in g_Wb (uint32 units)
#define EW1_OFF 0          // per layer 192*256*2 = 98304
#define EW2_OFF 983040     // per layer 128*128*2 = 32768
#define NW1_OFF 1310720    // per layer 128*256*2 = 65536
#define NW2_OFF 1966080    // per layer 32768
#define WB_TOTAL 2293760

// ---------------- device scratch ----------------
__device__ float g_h[NN * HD];
__device__ float g_ea[(size_t)NE * HD];
__device__ float g_P1[(size_t)NN * 256];
__device__ float g_P2[(size_t)NN * 256];
__device__ float g_agg[NN * HD];
__device__ float g_inv[NN];
__device__ int   g_cnt[NN];
__device__ int   g_row[NE];
__device__ int   g_col[NE];
__device__ uint32_t g_Wb[WB_TOTAL];

// ---------------- helpers ----------------
__device__ __forceinline__ float gelu(float x) { return x * normcdff(x); }

__device__ __forceinline__ uint32_t pack2(float a, float b) {
    uint32_t r;
    asm("cvt.rn.bf16x2.f32 %0, %1, %2;" : "=r"(r) : "f"(b), "f"(a));
    return r;
}

__device__ __forceinline__ void split2(float a, float b, uint32_t& hi, uint32_t& lo) {
    hi = pack2(a, b);
    float ra = a - __uint_as_float(hi << 16);
    float rb = b - __uint_as_float(hi & 0xffff0000u);
    lo = pack2(ra, rb);
}

__device__ __forceinline__ void mma_bf(float4& d, const uint32_t* a,
                                       uint32_t b0, uint32_t b1) {
    asm("mma.sync.aligned.m16n8k16.row.col.f32.bf16.bf16.f32 "
        "{%0,%1,%2,%3},{%4,%5,%6,%7},{%8,%9},{%0,%1,%2,%3};"
        : "+f"(d.x), "+f"(d.y), "+f"(d.z), "+f"(d.w)
        : "r"(a[0]), "r"(a[1]), "r"(a[2]), "r"(a[3]), "r"(b0), "r"(b1));
}

__device__ __forceinline__ void cpa16(void* sdst, const void* gsrc) {
    uint32_t sa = (uint32_t)__cvta_generic_to_shared(sdst);
    asm volatile("cp.async.cg.shared.global [%0], [%1], 16;" :: "r"(sa), "l"(gsrc));
}
__device__ __forceinline__ void cp_commit() {
    asm volatile("cp.async.commit_group;" ::: "memory");
}
__device__ __forceinline__ void cp_wait1() {
    asm volatile("cp.async.wait_group 1;" ::: "memory");
}
__device__ __forceinline__ void cp_wait0() {
    asm volatile("cp.async.wait_group 0;" ::: "memory");
}

// async-stage 16 rows x 512 u32 interleaved (ld 520) from [kp][n][2] global image
__device__ __forceinline__ void issueW16x256i(uint32_t* s,
                                              const uint32_t* __restrict__ P,
                                              int kpBase, int tid) {
    for (int t = tid; t < 16 * 128; t += 256) {
        int r = t >> 7, q = t & 127;
        cpa16(&s[r * 520 + q * 4], &P[((size_t)(kpBase + r) * 256) * 2 + q * 4]);
    }
    cp_commit();
}

// async-stage 8 rows x 512 u32 interleaved (ld 520)
__device__ __forceinline__ void issueW8x256i(uint32_t* s,
                                             const uint32_t* __restrict__ P,
                                             int kpBase, int tid) {
    for (int t = tid; t < 8 * 128; t += 256) {
        int r = t >> 7, q = t & 127;
        cpa16(&s[r * 520 + q * 4], &P[((size_t)(kpBase + r) * 256) * 2 + q * 4]);
    }
    cp_commit();
}

// async-stage 16 rows x 256 u32 interleaved (ld 264)
__device__ __forceinline__ void issueW16x128i(uint32_t* s,
                                              const uint32_t* __restrict__ P,
                                              int kpBase, int tid) {
    for (int t = tid; t < 16 * 64; t += 256) {
        int r = t >> 6, q = t & 63;
        cpa16(&s[r * 264 + q * 4], &P[((size_t)(kpBase + r) * 128) * 2 + q * 4]);
    }
    cp_commit();
}

// KS k16-steps of 3-term bf16-split MMA, interleaved (hi,lo) A and W.
template <int NT, int KS>
__device__ __forceinline__ void mma_chunk_i(
    const uint32_t* sA, int ldA, int aRow, int kpOff,
    const uint32_t* sW, int ldW, int cb,
    float4 (&acc)[2][NT], int lane) {
    int g = lane >> 2, tig = lane & 3;
#pragma unroll
    for (int ks = 0; ks < KS; ks++) {
        int cbase = kpOff + ks * 8;
        uint32_t ah[2][4], al[2][4];
#pragma unroll
        for (int mt = 0; mt < 2; mt++) {
            int r0 = aRow + mt * 16 + g, r1 = r0 + 8;
            uint2 v;
            v = *(const uint2*)&sA[r0 * ldA + (cbase + tig) * 2];
            ah[mt][0] = v.x; al[mt][0] = v.y;
            v = *(const uint2*)&sA[r1 * ldA + (cbase + tig) * 2];
            ah[mt][1] = v.x; al[mt][1] = v.y;
            v = *(const uint2*)&sA[r0 * ldA + (cbase + tig + 4) * 2];
            ah[mt][2] = v.x; al[mt][2] = v.y;
            v = *(const uint2*)&sA[r1 * ldA + (cbase + tig + 4) * 2];
            ah[mt][3] = v.x; al[mt][3] = v.y;
        }
        int wr0 = ks * 8 + tig, wr1 = wr0 + 4;
#pragma unroll
        for (int nt = 0; nt < NT; nt++) {
            int n = cb + nt * 8 + g;
            uint2 b0 = *(const uint2*)&sW[wr0 * ldW + n * 2];  // (bh0, bl0)
            uint2 b1 = *(const uint2*)&sW[wr1 * ldW + n * 2];  // (bh1, bl1)
#pragma unroll
            for (int mt = 0; mt < 2; mt++) {
                mma_bf(acc[mt][nt], ah[mt], b0.x, b1.x);
                mma_bf(acc[mt][nt], ah[mt], b0.y, b1.y);
                mma_bf(acc[mt][nt], al[mt], b0.x, b1.x);
            }
        }
    }
}

// ---------------- fused weight pre-split (interleaved images) ----------------
__global__ void k_prepAll(const float* __restrict__ eW1, const float* __restrict__ eW2,
                          const float* __restrict__ nW1, const float* __restrict__ nW2,
                          uint32_t* __restrict__ wb) {
    int l = blockIdx.y;
    int idx = blockIdx.x * 256 + threadIdx.x;   // < 114688
    const float* W;
    uint32_t* hp;
    int N, rel;
    if (idx < 49152)      { rel = idx;          W = eW1 + (size_t)l * 98304; hp = wb + EW1_OFF + l * 98304; N = 256; }
    else if (idx < 65536) { rel = idx - 49152;  W = eW2 + (size_t)l * 32768; hp = wb + EW2_OFF + l * 32768; N = 128; }
    else if (idx < 98304) { rel = idx - 65536;  W = nW1 + (size_t)l * 65536; hp = wb + NW1_OFF + l * 65536; N = 256; }
    else                  { rel = idx - 98304;  W = nW2 + (size_t)l * 32768; hp = wb + NW2_OFF + l * 32768; N = 128; }
    int kp = rel / N, n = rel - kp * N;
    float w0 = W[(size_t)(2 * kp) * N + n];
    float w1 = W[(size_t)(2 * kp + 1) * N + n];
    uint32_t hi, lo;
    split2(w0, w1, hi, lo);
    hp[((size_t)kp * N + n) * 2]     = hi;
    hp[((size_t)kp * N + n) * 2 + 1] = lo;
}

// ---------------- fused encoders + edge-index convert/deg ----------------
__device__ __forceinline__ float warpsum(float s) {
#pragma unroll
    for (int o = 16; o; o >>= 1) s += __shfl_xor_sync(0xffffffffu, s, o);
    return s;
}

#define CONV_BLOCKS ((NE + 127) / 128)

__global__ void k_encconv(const float* __restrict__ x, const float* __restrict__ encW,
                          const float* __restrict__ encb, const float* __restrict__ encg,
                          const float* __restrict__ encbt,
                          const float* __restrict__ eattr, const float* __restrict__ eeW,
                          const float* __restrict__ eeb,
                          const void* __restrict__ ei) {
    __shared__ float sx[8];
    __shared__ float red[8];
    __shared__ int sOk;
    int j = threadIdx.x;
    if (blockIdx.x < NN) {
        int n = blockIdx.x;
        if (j < 7) sx[j] = x[n * 7 + j];
        __syncthreads();
        float a = encb[j];
#pragma unroll
        for (int k = 0; k < 7; k++) a = fmaf(sx[k], encW[k * HD + j], a);
        int w = j >> 5, lane = j & 31;
        float s = warpsum(a);
        if (lane == 0) red[w] = s;
        __syncthreads();
        float m = (red[0] + red[1] + red[2] + red[3]) * (1.0f / HD);
        float d = a - m;
        float q = warpsum(d * d);
        if (lane == 0) red[4 + w] = q;
        __syncthreads();
        float var = (red[4] + red[5] + red[6] + red[7]) * (1.0f / HD);
        float t = d * rsqrtf(var + 1e-5f) * encg[j] + encbt[j];
        g_h[(size_t)n * HD + j] = gelu(t);
    } else if (blockIdx.x < NN + NE) {
        int e = blockIdx.x - NN;
        if (j < 8) sx[j] = eattr[e * 8 + j];
        __syncthreads();
        float a = eeb[j];
#pragma unroll
        for (int k = 0; k < 8; k++) a = fmaf(sx[k], eeW[k * HD + j], a);
        g_ea[(size_t)e * HD + j] = a;
    } else {
        if (j == 0) sOk = 1;
        __syncthreads();
        if (j < 64) {
            long long v = ((const long long*)ei)[j];
            if (v < 0 || v >= NN) sOk = 0;
        }
        __syncthreads();
        int is64 = sOk;
        int e = (blockIdx.x - NN - NE) * 128 + j;
        if (e < NE) {
            int r, c;
            if (is64) {
                const long long* p = (const long long*)ei;
                r = (int)p[e]; c = (int)p[NE + e];
            } else {
                const int* p = (const int*)ei;
                r = p[e]; c = p[NE + e];
            }
            g_row[e] = r;
            g_col[e] = c;
            atomicAdd(&g_cnt[c], 1);
        }
    }
}

__global__ void k_inv() {
    int n = blockIdx.x * blockDim.x + threadIdx.x;
    if (n < NN) {
        g_inv[n] = 1.0f / fmaxf((float)g_cnt[n], 1.0f);
        g_cnt[n] = 0;
    }
}

// ---------------- node projections P1 = h@W1a + b1, P2 = h@W1b (pipelined) ----------------
// smem (u32): hIl [0,8704) = 64x136 interleaved; wbuf [8704,25344): 2 x 8320 (ld 520)
__global__ void __launch_bounds__(256, 2) k_P(int w1Off, const float* __restrict__ b1) {
    extern __shared__ float sm[];
    uint32_t* hIl = (uint32_t*)sm;
    uint32_t* wbf = hIl + 8704;
    int tid = threadIdx.x, lane = tid & 31, wid = tid >> 5;
    int g = lane >> 2, tig = lane & 3;
    int base = blockIdx.x * 64;
    int part = blockIdx.y;
    const uint32_t* P = g_Wb + w1Off;
    float* out = part ? g_P2 : g_P1;

    issueW16x256i(wbf, P, part * 64, tid);
    issueW16x256i(wbf + 8320, P, part * 64 + 16, tid);

    for (int t = tid; t < 64 * 32; t += 256) {
        int i = t >> 5, q = t & 31;
        int n = base + i;
        float4 v = (n < NN) ? ((const float4*)g_h)[(size_t)n * 32 + q]
                            : make_float4(0, 0, 0, 0);
        uint32_t h0, l0, h1, l1;
        split2(v.x, v.y, h0, l0);
        split2(v.z, v.w, h1, l1);
        *(uint4*)&hIl[i * 136 + q * 4] = make_uint4(h0, l0, h1, l1);
    }
    __syncthreads();

    int rowg = (wid >> 2) * 32;
    int cb1 = (wid & 3) * 64;
    float4 acc[2][8];
#pragma unroll
    for (int mt = 0; mt < 2; mt++)
#pragma unroll
        for (int nt = 0; nt < 8; nt++) acc[mt][nt] = make_float4(0, 0, 0, 0);
    for (int kc = 0; kc < 4; kc++) {
        if (kc < 3) cp_wait1(); else cp_wait0();
        __syncthreads();
        uint32_t* wbuf = wbf + (kc & 1) * 8320;
        mma_chunk_i<8, 2>(hIl, 136, rowg, kc * 16, wbuf, 520, cb1, acc, lane);
        __syncthreads();
        if (kc + 2 < 4)
            issueW16x256i(wbf + (kc & 1) * 8320, P, part * 64 + (kc + 2) * 16, tid);
    }
#pragma unroll
    for (int mt = 0; mt < 2; mt++) {
        int r0 = base + rowg + mt * 16 + g;
#pragma unroll
        for (int nt = 0; nt < 8; nt++) {
            int C = cb1 + nt * 8 + 2 * tig;
            float bx = part ? 0.f : __ldg(&b1[C]);
            float by = part ? 0.f : __ldg(&b1[C + 1]);
            if (r0 < NN)
                *(float2*)&out[(size_t)r0 * 256 + C] =
                    make_float2(acc[mt][nt].x + bx, acc[mt][nt].y + by);
            if (r0 + 8 < NN)
                *(float2*)&out[(size_t)(r0 + 8) * 256 + C] =
                    make_float2(acc[mt][nt].z + bx, acc[mt][nt].w + by);
        }
    }
}

// single-pass LN reduction (sum + sumsq, one barrier)
#define LN_REDUCE(NTC, ACC, INVN)                                              \
    float p[2][2] = {{0, 0}, {0, 0}}, q[2][2] = {{0, 0}, {0, 0}};              \
    _Pragma("unroll")                                                          \
    for (int mt = 0; mt < 2; mt++)                                             \
        _Pragma("unroll")                                                      \
        for (int nt = 0; nt < NTC; nt++) {                                     \
            p[mt][0] += ACC[mt][nt].x + ACC[mt][nt].y;                         \
            q[mt][0] += ACC[mt][nt].x * ACC[mt][nt].x + ACC[mt][nt].y * ACC[mt][nt].y; \
            p[mt][1] += ACC[mt][nt].z + ACC[mt][nt].w;                         \
            q[mt][1] += ACC[mt][nt].z * ACC[mt][nt].z + ACC[mt][nt].w * ACC[mt][nt].w; \
        }                                                                      \
    _Pragma("unroll")                                                          \
    for (int mt = 0; mt < 2; mt++)                                             \
        _Pragma("unroll")                                                      \
        for (int h = 0; h < 2; h++) {                                          \
            p[mt][h] += __shfl_xor_sync(0xffffffffu, p[mt][h], 1);             \
            p[mt][h] += __shfl_xor_sync(0xffffffffu, p[mt][h], 2);             \
            q[mt][h] += __shfl_xor_sync(0xffffffffu, q[mt][h], 1);             \
            q[mt][h] += __shfl_xor_sync(0xffffffffu, q[mt][h], 2);             \
        }                                                                      \
    if (tig == 0)                                                              \
        _Pragma("unroll")                                                      \
        for (int mt = 0; mt < 2; mt++)                                         \
            _Pragma("unroll")                                                  \
            for (int h = 0; h < 2; h++) {                                      \
                int ri = (rowg + mt * 16 + h * 8 + g) * 4 + wcol;              \
                sRed[ri] = p[mt][h];                                           \
                sRed[256 + ri] = q[mt][h];                                     \
            }                                                                  \
    __syncthreads();                                                           \
    float m[2][2], rn[2][2];                                                   \
    _Pragma("unroll")                                                          \
    for (int mt = 0; mt < 2; mt++)                                             \
        _Pragma("unroll")                                                      \
        for (int h = 0; h < 2; h++) {                                          \
            int ri = (rowg + mt * 16 + h * 8 + g) * 4;                         \
            float4 s = *(const float4*)&sRed[ri];                              \
            float4 s2 = *(const float4*)&sRed[256 + ri];                       \
            float mm = (s.x + s.y + s.z + s.w) * (INVN);                       \
            float qq = (s2.x + s2.y + s2.z + s2.w) * (INVN);                   \
            m[mt][h] = mm;                                                     \
            rn[mt][h] = rsqrtf(qq - mm * mm + 1e-5f);                          \
        }

// ---------------- fused edge update (interleaved, cp.async pipelined) ----------------
// smem (u32): eIl [0,8704) = 64x136 | tIl [0,16896) = 64x264 (aliased)
//             G1 wbuf [8704,25344): 2 x 8320 (ld 520)
//             G2 wbuf [16896,25344): 2 x 4224 (ld 264)
__global__ void __launch_bounds__(256, 2) k_edge(
    int w1Off, int w2Off,
    const float* __restrict__ g1, const float* __restrict__ bt1,
    const float* __restrict__ b2, const float* __restrict__ g2,
    const float* __restrict__ bt2) {
    extern __shared__ float sm[];
    uint32_t* buf = (uint32_t*)sm;
    uint32_t* eIl = buf;
    uint32_t* tIl = buf;
    uint32_t* w1b = buf + 8704;
    uint32_t* w2b = buf + 16896;
    __shared__ int sRow[64], sCol[64];
    __shared__ __align__(16) float sRed[512];
    __shared__ float sP[896];
    int tid = threadIdx.x, lane = tid & 31, wid = tid >> 5;
    int g = lane >> 2, tig = lane & 3;
    int base = blockIdx.x * 64;
    const uint32_t* W1 = g_Wb + w1Off;
    const uint32_t* W2 = g_Wb + w2Off;

    issueW16x256i(w1b, W1, 128, tid);
    issueW16x256i(w1b + 8320, W1, 144, tid);

    if (tid < 64) { sRow[tid] = g_row[base + tid]; sCol[tid] = g_col[base + tid]; }
    for (int t = tid; t < 896; t += 256)
        sP[t] = (t < 256) ? g1[t] : (t < 512) ? bt1[t - 256]
              : (t < 640) ? b2[t - 512] : (t < 768) ? g2[t - 640] : bt2[t - 768];

    for (int t = tid; t < 64 * 32; t += 256) {   // ea tile -> interleaved bf16
        int e = t >> 5, q = t & 31;
        float4 v = ((const float4*)g_ea)[(size_t)(base + e) * 32 + q];
        uint32_t h0, l0, h1, l1;
        split2(v.x, v.y, h0, l0);
        split2(v.z, v.w, h1, l1);
        *(uint4*)&eIl[e * 136 + q * 4] = make_uint4(h0, l0, h1, l1);
    }
    __syncthreads();

    int rowg = (wid >> 2) * 32;
    int cb1 = (wid & 3) * 64;
    int wcol = wid & 3;

    // GEMM1 acc init: per-fragment gather of P1[row] + P2[col]
    float4 acc[2][8];
#pragma unroll
    for (int mt = 0; mt < 2; mt++) {
        int r0 = rowg + mt * 16 + g, r1 = r0 + 8;
        const float* p1a = &g_P1[(size_t)sRow[r0] * 256];
        const float* p2a = &g_P2[(size_t)sCol[r0] * 256];
        const float* p1b = &g_P1[(size_t)sRow[r1] * 256];
        const float* p2b = &g_P2[(size_t)sCol[r1] * 256];
#pragma unroll
        for (int nt = 0; nt < 8; nt++) {
            int C = cb1 + nt * 8 + 2 * tig;
            float2 u1 = *(const float2*)&p1a[C];
            float2 u2 = *(const float2*)&p2a[C];
            float2 v1 = *(const float2*)&p1b[C];
            float2 v2 = *(const float2*)&p2b[C];
            acc[mt][nt] = make_float4(u1.x + u2.x, u1.y + u2.y,
                                      v1.x + v2.x, v1.y + v2.y);
        }
    }

    for (int kc = 0; kc < 4; kc++) {
        if (kc < 3) cp_wait1(); else cp_wait0();
        __syncthreads();
        uint32_t* wbuf = w1b + (kc & 1) * 8320;
        mma_chunk_i<8, 2>(eIl, 136, rowg, kc * 16, wbuf, 520, cb1, acc, lane);
        __syncthreads();
        if (kc + 2 < 4)
            issueW16x256i(w1b + (kc & 1) * 8320, W1, 128 + (kc + 2) * 16, tid);
    }

    issueW16x128i(w2b, W2, 0, tid);
    issueW16x128i(w2b + 4224, W2, 16, tid);

    // LN(256) + GELU -> t (interleaved, aliased over eIl region)
    {
        LN_REDUCE(8, acc, 1.0f / 256)
#pragma unroll
        for (int mt = 0; mt < 2; mt++) {
            int r0 = rowg + mt * 16 + g;
#pragma unroll
            for (int nt = 0; nt < 8; nt++) {
                int C = cb1 + nt * 8 + 2 * tig;
                int cp = C >> 1;
                float gx = sP[C], gy = sP[C + 1];
                float bx = sP[256 + C], by = sP[256 + C + 1];
                float tx = gelu((acc[mt][nt].x - m[mt][0]) * rn[mt][0] * gx + bx);
                float ty = gelu((acc[mt][nt].y - m[mt][0]) * rn[mt][0] * gy + by);
                float tz = gelu((acc[mt][nt].z - m[mt][1]) * rn[mt][1] * gx + bx);
                float tw = gelu((acc[mt][nt].w - m[mt][1]) * rn[mt][1] * gy + by);
                uint32_t h0, l0, h1, l1;
                split2(tx, ty, h0, l0);
                split2(tz, tw, h1, l1);
                *(uint2*)&tIl[r0 * 264 + cp * 2] = make_uint2(h0, l0);
                *(uint2*)&tIl[(r0 + 8) * 264 + cp * 2] = make_uint2(h1, l1);
            }
        }
    }

    // GEMM2 pipelined: K=256, 8 chunks of 16 packed rows
    int cb2 = (wid & 3) * 32;
    float4 acc2[2][4];
#pragma unroll
    for (int mt = 0; mt < 2; mt++)
#pragma unroll
        for (int nt = 0; nt < 4; nt++) acc2[mt][nt] = make_float4(0, 0, 0, 0);
    for (int kc = 0; kc < 8; kc++) {
        if (kc < 7) cp_wait1(); else cp_wait0();
        __syncthreads();
        uint32_t* wbuf = w2b + (kc & 1) * 4224;
        mma_chunk_i<4, 2>(tIl, 264, rowg, kc * 16, wbuf, 264, cb2, acc2, lane);
        __syncthreads();
        if (kc + 2 < 8)
            issueW16x128i(w2b + (kc & 1) * 4224, W2, (kc + 2) * 16, tid);
    }

    // + b2, LN(128), residual (re-read g_ea), store + scatter
    {
#pragma unroll
        for (int mt = 0; mt < 2; mt++)
#pragma unroll
            for (int nt = 0; nt < 4; nt++) {
                int C = cb2 + nt * 8 + 2 * tig;
                acc2[mt][nt].x += sP[512 + C]; acc2[mt][nt].y += sP[512 + C + 1];
                acc2[mt][nt].z += sP[512 + C]; acc2[mt][nt].w += sP[512 + C + 1];
            }
        LN_REDUCE(4, acc2, 1.0f / 128)
#pragma unroll
        for (int mt = 0; mt < 2; mt++) {
            int r0 = rowg + mt * 16 + g;
            int r1 = r0 + 8;
#pragma unroll
            for (int nt = 0; nt < 4; nt++) {
                int C = cb2 + nt * 8 + 2 * tig;
                float gx = sP[640 + C], gy = sP[640 + C + 1];
                float bx = sP[768 + C], by = sP[768 + C + 1];
                float2 e0 = *(const float2*)&g_ea[(size_t)(base + r0) * HD + C];
                float2 e1 = *(const float2*)&g_ea[(size_t)(base + r1) * HD + C];
                float ox = e0.x + (acc2[mt][nt].x - m[mt][0]) * rn[mt][0] * gx + bx;
                float oy = e0.y + (acc2[mt][nt].y - m[mt][0]) * rn[mt][0] * gy + by;
                float oz = e1.x + (acc2[mt][nt].z - m[mt][1]) * rn[mt][1] * gx + bx;
                float ow = e1.y + (acc2[mt][nt].w - m[mt][1]) * rn[mt][1] * gy + by;
                *(float2*)&g_ea[(size_t)(base + r0) * HD + C] = make_float2(ox, oy);
                *(float2*)&g_ea[(size_t)(base + r1) * HD + C] = make_float2(oz, ow);
                float* a0 = &g_agg[(size_t)sCol[r0] * HD + C];
                float* a1 = &g_agg[(size_t)sCol[r1] * HD + C];
                asm volatile("red.global.add.v2.f32 [%0], {%1,%2};"
                             :: "l"(a0), "f"(ox), "f"(oy) : "memory");
                asm volatile("red.global.add.v2.f32 [%0], {%1,%2};"
                             :: "l"(a1), "f"(oz), "f"(ow) : "memory");
            }
        }
    }
}

// ---------------- fused node update (interleaved, pipelined) ----------------
// smem (u32): aIl [0,16896) = 64x264; G1 wbuf [16896,25216): 2x4160 (8 rows, ld 520)
//             G2 wbuf [16896,25344): 2x4224 (ld 264)
__global__ void __launch_bounds__(256, 2) k_node(
    int w1Off, int w2Off,
    const float* __restrict__ b1, const float* __restrict__ g1,
    const float* __restrict__ bt1, const float* __restrict__ b2,
    const float* __restrict__ g2, const float* __restrict__ bt2) {
    extern __shared__ float sm[];
    uint32_t* aIl = (uint32_t*)sm;
    uint32_t* w1b = aIl + 16896;
    uint32_t* w2b = aIl + 16896;
    uint32_t* tIl = aIl;
    __shared__ __align__(16) float sRed[512];
    __shared__ float sP[1152];
    int tid = threadIdx.x, lane = tid & 31, wid = tid >> 5;
    int g = lane >> 2, tig = lane & 3;
    int base = blockIdx.x * 64;
    const uint32_t* W1 = g_Wb + w1Off;
    const uint32_t* W2 = g_Wb + w2Off;

    issueW8x256i(w1b, W1, 0, tid);
    issueW8x256i(w1b + 4160, W1, 8, tid);

    for (int t = tid; t < 1152; t += 256)
        sP[t] = (t < 256) ? b1[t] : (t < 512) ? g1[t - 256] : (t < 768) ? bt1[t - 512]
              : (t < 896) ? b2[t - 768] : (t < 1024) ? g2[t - 896] : bt2[t - 1024];

    for (int t = tid; t < 64 * 32; t += 256) {
        int i = t >> 5, q = t & 31;
        int n = base + i;
        float4 v = (n < NN) ? ((const float4*)g_h)[(size_t)n * 32 + q]
                            : make_float4(0, 0, 0, 0);
        uint32_t h0, l0, h1, l1;
        split2(v.x, v.y, h0, l0);
        split2(v.z, v.w, h1, l1);
        *(uint4*)&aIl[i * 264 + q * 4] = make_uint4(h0, l0, h1, l1);
    }
    for (int t = tid; t < 64 * 32; t += 256) {
        int i = t >> 5, q = t & 31;
        int n = base + i;
        float4 v = make_float4(0, 0, 0, 0);
        if (n < NN) {
            float4* ap = (float4*)&g_agg[(size_t)n * HD + q * 4];
            v = *ap;
            float iv = g_inv[n];
            v.x *= iv; v.y *= iv; v.z *= iv; v.w *= iv;
            *ap = make_float4(0, 0, 0, 0);
        }
        uint32_t h0, l0, h1, l1;
        split2(v.x, v.y, h0, l0);
        split2(v.z, v.w, h1, l1);
        *(uint4*)&aIl[i * 264 + 128 + q * 4] = make_uint4(h0, l0, h1, l1);
    }
    __syncthreads();

    int rowg = (wid >> 2) * 32;
    int cb1 = (wid & 3) * 64;
    int wcol = wid & 3;

    // GEMM1 (M=64, N=256, K=256): 16 pipelined chunks of 8 kp
    float4 acc[2][8];
#pragma unroll
    for (int mt = 0; mt < 2; mt++)
#pragma unroll
        for (int nt = 0; nt < 8; nt++) {
            int C = cb1 + nt * 8 + 2 * tig;
            acc[mt][nt] = make_float4(sP[C], sP[C + 1], sP[C], sP[C + 1]);
        }
    for (int kc = 0; kc < 16; kc++) {
        if (kc < 15) cp_wait1(); else cp_wait0();
        __syncthreads();
        uint32_t* wbuf = w1b + (kc & 1) * 4160;
        mma_chunk_i<8, 1>(aIl, 264, rowg, kc * 8, wbuf, 520, cb1, acc, lane);
        __syncthreads();
        if (kc + 2 < 16)
            issueW8x256i(w1b + (kc & 1) * 4160, W1, (kc + 2) * 8, tid);
    }

    issueW16x128i(w2b, W2, 0, tid);
    issueW16x128i(w2b + 4224, W2, 16, tid);

    // LN(256) + GELU -> t interleaved (aliased on A)
    {
        LN_REDUCE(8, acc, 1.0f / 256)
#pragma unroll
        for (int mt = 0; mt < 2; mt++) {
            int r0 = rowg + mt * 16 + g;
#pragma unroll
            for (int nt = 0; nt < 8; nt++) {
                int C = cb1 + nt * 8 + 2 * tig;
                int cp = C >> 1;
                float gx = sP[256 + C], gy = sP[256 + C + 1];
                float bx = sP[512 + C], by = sP[512 + C + 1];
                float tx = gelu((acc[mt][nt].x - m[mt][0]) * rn[mt][0] * gx + bx);
                float ty = gelu((acc[mt][nt].y - m[mt][0]) * rn[mt][0] * gy + by);
                float tz = gelu((acc[mt][nt].z - m[mt][1]) * rn[mt][1] * gx + bx);
                float tw = gelu((acc[mt][nt].w - m[mt][1]) * rn[mt][1] * gy + by);
                uint32_t h0, l0, h1, l1;
                split2(tx, ty, h0, l0);
                split2(tz, tw, h1, l1);
                *(uint2*)&tIl[r0 * 264 + cp * 2] = make_uint2(h0, l0);
                *(uint2*)&tIl[(r0 + 8) * 264 + cp * 2] = make_uint2(h1, l1);
            }
        }
    }

    // GEMM2 (M=64, N=128, K=256): 8 pipelined chunks of 16 kp
    int cb2 = (wid & 3) * 32;
    float4 acc2[2][4];
#pragma unroll
    for (int mt = 0; mt < 2; mt++)
#pragma unroll
        for (int nt = 0; nt < 4; nt++) acc2[mt][nt] = make_float4(0, 0, 0, 0);
    for (int kc = 0; kc < 8; kc++) {
        if (kc < 7) cp_wait1(); else cp_wait0();
        __syncthreads();
        uint32_t* wbuf = w2b + (kc & 1) * 4224;
        mma_chunk_i<4, 2>(tIl, 264, rowg, kc * 16, wbuf, 264, cb2, acc2, lane);
        __syncthreads();
        if (kc + 2 < 8)
            issueW16x128i(w2b + (kc & 1) * 4224, W2, (kc + 2) * 16, tid);
    }

    // + b2, LN(128), residual from g_h, store h
    {
#pragma unroll
        for (int mt = 0; mt < 2; mt++)
#pragma unroll
            for (int nt = 0; nt < 4; nt++) {
                int C = cb2 + nt * 8 + 2 * tig;
                acc2[mt][nt].x += sP[768 + C]; acc2[mt][nt].y += sP[768 + C + 1];
                acc2[mt][nt].z += sP[768 + C]; acc2[mt][nt].w += sP[768 + C + 1];
            }
        LN_REDUCE(4, acc2, 1.0f / 128)
#pragma unroll
        for (int mt = 0; mt < 2; mt++) {
            int r0 = rowg + mt * 16 + g;
            int r1 = r0 + 8;
            int n0 = base + r0, n1 = base + r1;
#pragma unroll
            for (int nt = 0; nt < 4; nt++) {
                int C = cb2 + nt * 8 + 2 * tig;
                float gx = sP[896 + C], gy = sP[896 + C + 1];
                float bx = sP[1024 + C], by = sP[1024 + C + 1];
                if (n0 < NN) {
                    float2 hr = *(const float2*)&g_h[(size_t)n0 * HD + C];
                    float ox = hr.x + (acc2[mt][nt].x - m[mt][0]) * rn[mt][0] * gx + bx;
                    float oy = hr.y + (acc2[mt][nt].y - m[mt][0]) * rn[mt][0] * gy + by;
                    *(float2*)&g_h[(size_t)n0 * HD + C] = make_float2(ox, oy);
                }
                if (n1 < NN) {
                    float2 hr = *(const float2*)&g_h[(size_t)n1 * HD + C];
                    float oz = hr.x + (acc2[mt][nt].z - m[mt][1]) * rn[mt][1] * gx + bx;
                    float ow = hr.y + (acc2[mt][nt].w - m[mt][1]) * rn[mt][1] * gy + by;
                    *(float2*)&g_h[(size_t)n1 * HD + C] = make_float2(oz, ow);
                }
            }
        }
    }
}

// ---------------- decoder ----------------
__global__ void k_dec(const float* __restrict__ W1, const float* __restrict__ b1,
                      const float* __restrict__ W2, const float* __restrict__ b2,
                      float* __restrict__ out) {
    int n = blockIdx.x, j = threadIdx.x;
    __shared__ float sh[128];
    __shared__ float st[128];
    sh[j] = g_h[(size_t)n * HD + j];
    __syncthreads();
    float a = b1[j];
#pragma unroll 8
    for (int k = 0; k < 128; k++) a = fmaf(sh[k], W1[k * HD + j], a);
    st[j] = gelu(a);
    __syncthreads();
    int w = j >> 5, lane = j & 31;
    float s = 0;
#pragma unroll
    for (int k = lane; k < 128; k += 32) s = fmaf(st[k], W2[k * 4 + w], s);
    s = warpsum(s);
    if (lane == 0) out[(size_t)n * 4 + w] = s + b2[w];
}

// ---------------- launch ----------------
extern "C" void kernel_launch(void* const* d_in, const int* in_sizes, int n_in,
                              void* d_out, int out_size) {
    (void)in_sizes; (void)n_in; (void)out_size;
    const float* x       = (const float*)d_in[0];
    const void*  ei      = d_in[1];
    const float* eattr   = (const float*)d_in[2];
    const float* enc_W   = (const float*)d_in[3];
    const float* enc_b   = (const float*)d_in[4];
    const float* enc_g   = (const float*)d_in[5];
    const float* enc_bt  = (const float*)d_in[6];
    const float* ee_W    = (const float*)d_in[7];
    const float* ee_b    = (const float*)d_in[8];
    const float* eW1     = (const float*)d_in[9];
    const float* eb1     = (const float*)d_in[10];
    const float* eg1     = (const float*)d_in[11];
    const float* ebt1    = (const float*)d_in[12];
    const float* eW2     = (const float*)d_in[13];
    const float* eb2     = (const float*)d_in[14];
    const float* eg2     = (const float*)d_in[15];
    const float* ebt2    = (const float*)d_in[16];
    const float* nW1     = (const float*)d_in[17];
    const float* nb1     = (const float*)d_in[18];
    const float* ng1     = (const float*)d_in[19];
    const float* nbt1    = (const float*)d_in[20];
    const float* nW2     = (const float*)d_in[21];
    const float* nb2     = (const float*)d_in[22];
    const float* ng2     = (const float*)d_in[23];
    const float* nbt2    = (const float*)d_in[24];
    const float* dec_W1  = (const float*)d_in[25];
    const float* dec_b1  = (const float*)d_in[26];
    const float* dec_W2  = (const float*)d_in[27];
    const float* dec_b2  = (const float*)d_in[28];

    cudaFuncSetAttribute(k_edge, cudaFuncAttributeMaxDynamicSharedMemorySize, EDGE_SMEM);
    cudaFuncSetAttribute(k_node, cudaFuncAttributeMaxDynamicSharedMemorySize, NODE_SMEM);
    cudaFuncSetAttribute(k_P,    cudaFuncAttributeMaxDynamicSharedMemorySize, P_SMEM);

    uint32_t* wb = nullptr;
    cudaGetSymbolAddress((void**)&wb, g_Wb);

    const int nodeBlocks = (NN + 63) / 64;  // 782

    // k_edge kept at my launch index 3 (harness offset +2 -> ncu -s5 captures it)
    k_prepAll<<<dim3(448, 10), 256>>>(eW1, eW2, nW1, nW2, wb);         // 0
    k_encconv<<<NN + NE + CONV_BLOCKS, 128>>>(x, enc_W, enc_b, enc_g,
        enc_bt, eattr, ee_W, ee_b, ei);                                // 1
    k_P<<<dim3(nodeBlocks, 2), 256, P_SMEM>>>(EW1_OFF, eb1);           // 2
    k_edge<<<NE / 64, 256, EDGE_SMEM>>>(EW1_OFF, EW2_OFF,
        eg1, ebt1, eb2, eg2, ebt2);                                    // 3 <- profiled
    k_inv<<<(NN + 255) / 256, 256>>>();                                // 4
    k_node<<<nodeBlocks, 256, NODE_SMEM>>>(NW1_OFF, NW2_OFF,
        nb1, ng1, nbt1, nb2, ng2, nbt2);                               // 5

    for (int l = 1; l < 10; l++) {
        k_P<<<dim3(nodeBlocks, 2), 256, P_SMEM>>>(EW1_OFF + l * 98304, eb1 + l * 256);
        k_edge<<<NE / 64, 256, EDGE_SMEM>>>(
            EW1_OFF + l * 98304, EW2_OFF + l * 32768,
            eg1 + l * 256, ebt1 + l * 256,
            eb2 + l * 128, eg2 + l * 128, ebt2 + l * 128);
        k_node<<<nodeBlocks, 256, NODE_SMEM>>>(
            NW1_OFF + l * 65536, NW2_OFF + l * 32768,
            nb1 + l * 256, ng1 + l * 256, nbt1 + l * 256,
            nb2 + l * 128, ng2 + l * 128, nbt2 + l * 128);
    }
    k_dec<<<NN, 128>>>(dec_W1, dec_b1, dec_W2, dec_b2, (float*)d_out);
}

// round 13
// speedup vs baseline: 1.0821x; 1.0821x over previous
#include <cuda_runtime.h>
#include <cuda_bf16.h>
#include <cstdint>

#define NN 50000
#define NE 600000
#define HD 128

#define EDGE_SMEM 101376   // 25344 u32
#define NODE_SMEM 101376
#define P_SMEM    101376

// packed-weight plane offsets in g_Wb (uint32 units)
#define EW1_OFF 0          // per layer 2*192*256 = 98304
#define EW2_OFF 983040     // per layer 2*128*128 = 32768
#define NW1_OFF 1310720    // per layer 2*128*256 = 65536
#define NW2_OFF 1966080    // per layer 32768
#define WB_TOTAL 2293760

// ---------------- device scratch ----------------
__device__ float g_h[NN * HD];
__device__ float g_ea[(size_t)NE * HD];
__device__ float g_P1[(size_t)NN * 256];
__device__ float g_P2[(size_t)NN * 256];
__device__ float g_agg[NN * HD];
__device__ float g_inv[NN];
__device__ int   g_cnt[NN];
__device__ int   g_row[NE];
__device__ int   g_col[NE];
__device__ uint32_t g_Wb[WB_TOTAL];

// ---------------- helpers ----------------
__device__ __forceinline__ float gelu(float x) { return x * normcdff(x); }

__device__ __forceinline__ uint32_t pack2(float a, float b) {
    uint32_t r;
    asm("cvt.rn.bf16x2.f32 %0, %1, %2;" : "=r"(r) : "f"(b), "f"(a));
    return r;
}

__device__ __forceinline__ void split2(float a, float b, uint32_t& hi, uint32_t& lo) {
    hi = pack2(a, b);
    float ra = a - __uint_as_float(hi << 16);
    float rb = b - __uint_as_float(hi & 0xffff0000u);
    lo = pack2(ra, rb);
}

__device__ __forceinline__ void mma_bf(float4& d, const uint32_t* a,
                                       uint32_t b0, uint32_t b1) {
    asm("mma.sync.aligned.m16n8k16.row.col.f32.bf16.bf16.f32 "
        "{%0,%1,%2,%3},{%4,%5,%6,%7},{%8,%9},{%0,%1,%2,%3};"
        : "+f"(d.x), "+f"(d.y), "+f"(d.z), "+f"(d.w)
        : "r"(a[0]), "r"(a[1]), "r"(a[2]), "r"(a[3]), "r"(b0), "r"(b1));
}

__device__ __forceinline__ void cpa16(void* sdst, const void* gsrc) {
    uint32_t sa = (uint32_t)__cvta_generic_to_shared(sdst);
    asm volatile("cp.async.cg.shared.global [%0], [%1], 16;" :: "r"(sa), "l"(gsrc));
}
__device__ __forceinline__ void cp_commit() {
    asm volatile("cp.async.commit_group;" ::: "memory");
}
__device__ __forceinline__ void cp_wait1() {
    asm volatile("cp.async.wait_group 1;" ::: "memory");
}
__device__ __forceinline__ void cp_wait0() {
    asm volatile("cp.async.wait_group 0;" ::: "memory");
}

// async-stage 16 rows x 256 u32 (hi at s, lo at s+4160, ld 260)
__device__ __forceinline__ void issueW16x256(uint32_t* s,
                                             const uint32_t* __restrict__ hiP,
                                             const uint32_t* __restrict__ loP,
                                             int kpBase, int tid) {
    for (int t = tid; t < 16 * 64; t += 256) {
        int r = t >> 6, q = t & 63;
        cpa16(&s[r * 260 + q * 4], &hiP[(size_t)(kpBase + r) * 256 + q * 4]);
        cpa16(&s[4160 + r * 260 + q * 4], &loP[(size_t)(kpBase + r) * 256 + q * 4]);
    }
    cp_commit();
}

// async-stage 8 rows x 256 u32 (hi at s, lo at s+2080, ld 260)
__device__ __forceinline__ void issueW8x256(uint32_t* s,
                                            const uint32_t* __restrict__ hiP,
                                            const uint32_t* __restrict__ loP,
                                            int kpBase, int tid) {
    for (int t = tid; t < 8 * 64; t += 256) {
        int r = t >> 6, q = t & 63;
        cpa16(&s[r * 260 + q * 4], &hiP[(size_t)(kpBase + r) * 256 + q * 4]);
        cpa16(&s[2080 + r * 260 + q * 4], &loP[(size_t)(kpBase + r) * 256 + q * 4]);
    }
    cp_commit();
}

// async-stage 16 rows x 128 u32 (hi at s, lo at s+2112, ld 132)
__device__ __forceinline__ void issueW16x128(uint32_t* s,
                                             const uint32_t* __restrict__ hiP,
                                             const uint32_t* __restrict__ loP,
                                             int kpBase, int tid) {
    for (int t = tid; t < 16 * 32; t += 256) {
        int r = t >> 5, q = t & 31;
        cpa16(&s[r * 132 + q * 4], &hiP[(size_t)(kpBase + r) * 128 + q * 4]);
        cpa16(&s[2112 + r * 132 + q * 4], &loP[(size_t)(kpBase + r) * 128 + q * 4]);
    }
    cp_commit();
}

// KS k16-steps of 3-term bf16-split MMA (KS=2 -> 16 kp chunk, KS=1 -> 8 kp chunk)
template <int NT, int KS>
__device__ __forceinline__ void mma_chunk_bf(
    const uint32_t* sAh, const uint32_t* sAl, int ldA, int aRow, int kpOff,
    const uint32_t* sWh, const uint32_t* sWl, int ldW, int cb,
    float4 (&acc)[2][NT], int lane) {
    int g = lane >> 2, tig = lane & 3;
#pragma unroll
    for (int ks = 0; ks < KS; ks++) {
        int cbase = kpOff + ks * 8;
        uint32_t ah[2][4], al[2][4];
#pragma unroll
        for (int mt = 0; mt < 2; mt++) {
            int r0 = aRow + mt * 16 + g, r1 = r0 + 8;
            ah[mt][0] = sAh[r0 * ldA + cbase + tig];
            ah[mt][1] = sAh[r1 * ldA + cbase + tig];
            ah[mt][2] = sAh[r0 * ldA + cbase + tig + 4];
            ah[mt][3] = sAh[r1 * ldA + cbase + tig + 4];
            al[mt][0] = sAl[r0 * ldA + cbase + tig];
            al[mt][1] = sAl[r1 * ldA + cbase + tig];
            al[mt][2] = sAl[r0 * ldA + cbase + tig + 4];
            al[mt][3] = sAl[r1 * ldA + cbase + tig + 4];
        }
        int wr0 = ks * 8 + tig, wr1 = wr0 + 4;
#pragma unroll
        for (int nt = 0; nt < NT; nt++) {
            int n = cb + nt * 8 + g;
            uint32_t bh0 = sWh[wr0 * ldW + n], bh1 = sWh[wr1 * ldW + n];
            uint32_t bl0 = sWl[wr0 * ldW + n], bl1 = sWl[wr1 * ldW + n];
#pragma unroll
            for (int mt = 0; mt < 2; mt++) {
                mma_bf(acc[mt][nt], ah[mt], bh0, bh1);
                mma_bf(acc[mt][nt], ah[mt], bl0, bl1);
                mma_bf(acc[mt][nt], al[mt], bh0, bh1);
            }
        }
    }
}

// ---------------- fused weight pre-split (all 4 groups, one launch) ----------------
__global__ void k_prepAll(const float* __restrict__ eW1, const float* __restrict__ eW2,
                          const float* __restrict__ nW1, const float* __restrict__ nW2,
                          uint32_t* __restrict__ wb) {
    int l = blockIdx.y;
    int idx = blockIdx.x * 256 + threadIdx.x;   // < 114688
    const float* W;
    uint32_t* hp;
    int KP, N, rel;
    if (idx < 49152)      { rel = idx;          W = eW1 + (size_t)l * 98304; hp = wb + EW1_OFF + l * 98304; KP = 192; N = 256; }
    else if (idx < 65536) { rel = idx - 49152;  W = eW2 + (size_t)l * 32768; hp = wb + EW2_OFF + l * 32768; KP = 128; N = 128; }
    else if (idx < 98304) { rel = idx - 65536;  W = nW1 + (size_t)l * 65536; hp = wb + NW1_OFF + l * 65536; KP = 128; N = 256; }
    else                  { rel = idx - 98304;  W = nW2 + (size_t)l * 32768; hp = wb + NW2_OFF + l * 32768; KP = 128; N = 128; }
    int kp = rel / N, n = rel - kp * N;
    float w0 = W[(size_t)(2 * kp) * N + n];
    float w1 = W[(size_t)(2 * kp + 1) * N + n];
    uint32_t hi, lo;
    split2(w0, w1, hi, lo);
    hp[(size_t)kp * N + n] = hi;
    hp[(size_t)KP * N + (size_t)kp * N + n] = lo;
}

// ---------------- fused encoders + edge-index convert/deg ----------------
__device__ __forceinline__ float warpsum(float s) {
#pragma unroll
    for (int o = 16; o; o >>= 1) s += __shfl_xor_sync(0xffffffffu, s, o);
    return s;
}

#define CONV_BLOCKS ((NE + 127) / 128)

__global__ void k_encconv(const float* __restrict__ x, const float* __restrict__ encW,
                          const float* __restrict__ encb, const float* __restrict__ encg,
                          const float* __restrict__ encbt,
                          const float* __restrict__ eattr, const float* __restrict__ eeW,
                          const float* __restrict__ eeb,
                          const void* __restrict__ ei) {
    __shared__ float sx[8];
    __shared__ float red[8];
    __shared__ int sOk;
    int j = threadIdx.x;
    if (blockIdx.x < NN) {
        int n = blockIdx.x;
        if (j < 7) sx[j] = x[n * 7 + j];
        __syncthreads();
        float a = encb[j];
#pragma unroll
        for (int k = 0; k < 7; k++) a = fmaf(sx[k], encW[k * HD + j], a);
        int w = j >> 5, lane = j & 31;
        float s = warpsum(a);
        if (lane == 0) red[w] = s;
        __syncthreads();
        float m = (red[0] + red[1] + red[2] + red[3]) * (1.0f / HD);
        float d = a - m;
        float q = warpsum(d * d);
        if (lane == 0) red[4 + w] = q;
        __syncthreads();
        float var = (red[4] + red[5] + red[6] + red[7]) * (1.0f / HD);
        float t = d * rsqrtf(var + 1e-5f) * encg[j] + encbt[j];
        g_h[(size_t)n * HD + j] = gelu(t);
    } else if (blockIdx.x < NN + NE) {
        int e = blockIdx.x - NN;
        if (j < 8) sx[j] = eattr[e * 8 + j];
        __syncthreads();
        float a = eeb[j];
#pragma unroll
        for (int k = 0; k < 8; k++) a = fmaf(sx[k], eeW[k * HD + j], a);
        g_ea[(size_t)e * HD + j] = a;
    } else {
        if (j == 0) sOk = 1;
        __syncthreads();
        if (j < 64) {
            long long v = ((const long long*)ei)[j];
            if (v < 0 || v >= NN) sOk = 0;
        }
        __syncthreads();
        int is64 = sOk;
        int e = (blockIdx.x - NN - NE) * 128 + j;
        if (e < NE) {
            int r, c;
            if (is64) {
                const long long* p = (const long long*)ei;
                r = (int)p[e]; c = (int)p[NE + e];
            } else {
                const int* p = (const int*)ei;
                r = p[e]; c = p[NE + e];
            }
            g_row[e] = r;
            g_col[e] = c;
            atomicAdd(&g_cnt[c], 1);
        }
    }
}

__global__ void k_inv() {
    int n = blockIdx.x * blockDim.x + threadIdx.x;
    if (n < NN) {
        g_inv[n] = 1.0f / fmaxf((float)g_cnt[n], 1.0f);
        g_cnt[n] = 0;
    }
}

// ---------------- node projections P1 = h@W1a + b1, P2 = h@W1b (pipelined) ----------------
// smem (u32): hHi [0,4352) hLo [4352,8704) wbuf [8704,25344): 2 x 8320
__global__ void __launch_bounds__(256, 2) k_P(int w1Off, const float* __restrict__ b1) {
    extern __shared__ float sm[];
    uint32_t* hHi = (uint32_t*)sm;
    uint32_t* hLo = hHi + 4352;
    uint32_t* wbf = hHi + 8704;
    int tid = threadIdx.x, lane = tid & 31, wid = tid >> 5;
    int g = lane >> 2, tig = lane & 3;
    int base = blockIdx.x * 64;
    int part = blockIdx.y;
    const uint32_t* hiP = g_Wb + w1Off;
    const uint32_t* loP = hiP + 49152;
    float* out = part ? g_P2 : g_P1;

    issueW16x256(wbf, hiP, loP, part * 64, tid);
    issueW16x256(wbf + 8320, hiP, loP, part * 64 + 16, tid);

    for (int t = tid; t < 64 * 32; t += 256) {
        int i = t >> 5, q = t & 31;
        int n = base + i;
        float4 v = (n < NN) ? ((const float4*)g_h)[(size_t)n * 32 + q]
                            : make_float4(0, 0, 0, 0);
        uint32_t h0, l0, h1, l1;
        split2(v.x, v.y, h0, l0);
        split2(v.z, v.w, h1, l1);
        *(uint2*)&hHi[i * 68 + 2 * q] = make_uint2(h0, h1);
        *(uint2*)&hLo[i * 68 + 2 * q] = make_uint2(l0, l1);
    }
    __syncthreads();

    int rowg = (wid >> 2) * 32;
    int cb1 = (wid & 3) * 64;
    float4 acc[2][8];
#pragma unroll
    for (int mt = 0; mt < 2; mt++)
#pragma unroll
        for (int nt = 0; nt < 8; nt++) acc[mt][nt] = make_float4(0, 0, 0, 0);
    for (int kc = 0; kc < 4; kc++) {
        if (kc < 3) cp_wait1(); else cp_wait0();
        __syncthreads();
        uint32_t* wbuf = wbf + (kc & 1) * 8320;
        mma_chunk_bf<8, 2>(hHi, hLo, 68, rowg, kc * 16, wbuf, wbuf + 4160, 260, cb1, acc, lane);
        __syncthreads();
        if (kc + 2 < 4)
            issueW16x256(wbf + (kc & 1) * 8320, hiP, loP, part * 64 + (kc + 2) * 16, tid);
    }
#pragma unroll
    for (int mt = 0; mt < 2; mt++) {
        int r0 = base + rowg + mt * 16 + g;
#pragma unroll
        for (int nt = 0; nt < 8; nt++) {
            int C = cb1 + nt * 8 + 2 * tig;
            float bx = part ? 0.f : __ldg(&b1[C]);
            float by = part ? 0.f : __ldg(&b1[C + 1]);
            if (r0 < NN)
                *(float2*)&out[(size_t)r0 * 256 + C] =
                    make_float2(acc[mt][nt].x + bx, acc[mt][nt].y + by);
            if (r0 + 8 < NN)
                *(float2*)&out[(size_t)(r0 + 8) * 256 + C] =
                    make_float2(acc[mt][nt].z + bx, acc[mt][nt].w + by);
        }
    }
}

// single-pass LN reduction (sum + sumsq, one barrier)
#define LN_REDUCE(NTC, ACC, INVN)                                              \
    float p[2][2] = {{0, 0}, {0, 0}}, q[2][2] = {{0, 0}, {0, 0}};              \
    _Pragma("unroll")                                                          \
    for (int mt = 0; mt < 2; mt++)                                             \
        _Pragma("unroll")                                                      \
        for (int nt = 0; nt < NTC; nt++) {                                     \
            p[mt][0] += ACC[mt][nt].x + ACC[mt][nt].y;                         \
            q[mt][0] += ACC[mt][nt].x * ACC[mt][nt].x + ACC[mt][nt].y * ACC[mt][nt].y; \
            p[mt][1] += ACC[mt][nt].z + ACC[mt][nt].w;                         \
            q[mt][1] += ACC[mt][nt].z * ACC[mt][nt].z + ACC[mt][nt].w * ACC[mt][nt].w; \
        }                                                                      \
    _Pragma("unroll")                                                          \
    for (int mt = 0; mt < 2; mt++)                                             \
        _Pragma("unroll")                                                      \
        for (int h = 0; h < 2; h++) {                                          \
            p[mt][h] += __shfl_xor_sync(0xffffffffu, p[mt][h], 1);             \
            p[mt][h] += __shfl_xor_sync(0xffffffffu, p[mt][h], 2);             \
            q[mt][h] += __shfl_xor_sync(0xffffffffu, q[mt][h], 1);             \
            q[mt][h] += __shfl_xor_sync(0xffffffffu, q[mt][h], 2);             \
        }                                                                      \
    if (tig == 0)                                                              \
        _Pragma("unroll")                                                      \
        for (int mt = 0; mt < 2; mt++)                                         \
            _Pragma("unroll")                                                  \
            for (int h = 0; h < 2; h++) {                                      \
                int ri = (rowg + mt * 16 + h * 8 + g) * 4 + wcol;              \
                sRed[ri] = p[mt][h];                                           \
                sRed[256 + ri] = q[mt][h];                                     \
            }                                                                  \
    __syncthreads();                                                           \
    float m[2][2], rn[2][2];                                                   \
    _Pragma("unroll")                                                          \
    for (int mt = 0; mt < 2; mt++)                                             \
        _Pragma("unroll")                                                      \
        for (int h = 0; h < 2; h++) {                                          \
            int ri = (rowg + mt * 16 + h * 8 + g) * 4;                         \
            float4 s = *(const float4*)&sRed[ri];                              \
            float4 s2 = *(const float4*)&sRed[256 + ri];                       \
            float mm = (s.x + s.y + s.z + s.w) * (INVN);                       \
            float qq = (s2.x + s2.y + s2.z + s2.w) * (INVN);                   \
            m[mt][h] = mm;                                                     \
            rn[mt][h] = rsqrtf(qq - mm * mm + 1e-5f);                          \
        }

// ---------------- fused edge update (R11 proven, cp.async pipelined) ----------------
// smem (u32): eHi [0,4352) eLo [4352,8704) | tHi [0,8448) tLo [8448,16896)
//             G1 wbuf [8704,25344): 2 x 8320 ; G2 wbuf [16896,25344): 2 x 4224
__global__ void __launch_bounds__(256, 2) k_edge(
    int w1Off, int w2Off,
    const float* __restrict__ g1, const float* __restrict__ bt1,
    const float* __restrict__ b2, const float* __restrict__ g2,
    const float* __restrict__ bt2) {
    extern __shared__ float sm[];
    uint32_t* buf = (uint32_t*)sm;
    uint32_t* eHi = buf;
    uint32_t* eLo = buf + 4352;
    uint32_t* tHi = buf;
    uint32_t* tLo = buf + 8448;
    uint32_t* w1b = buf + 8704;
    uint32_t* w2b = buf + 16896;
    __shared__ int sRow[64], sCol[64];
    __shared__ __align__(16) float sRed[512];
    __shared__ float sP[896];
    int tid = threadIdx.x, lane = tid & 31, wid = tid >> 5;
    int g = lane >> 2, tig = lane & 3;
    int base = blockIdx.x * 64;
    const uint32_t* hi1 = g_Wb + w1Off;
    const uint32_t* lo1 = hi1 + 49152;
    const uint32_t* hi2 = g_Wb + w2Off;
    const uint32_t* lo2 = hi2 + 16384;

    issueW16x256(w1b, hi1, lo1, 128, tid);
    issueW16x256(w1b + 8320, hi1, lo1, 144, tid);

    if (tid < 64) { sRow[tid] = g_row[base + tid]; sCol[tid] = g_col[base + tid]; }
    for (int t = tid; t < 896; t += 256)
        sP[t] = (t < 256) ? g1[t] : (t < 512) ? bt1[t - 256]
              : (t < 640) ? b2[t - 512] : (t < 768) ? g2[t - 640] : bt2[t - 768];

    for (int t = tid; t < 64 * 32; t += 256) {   // ea tile -> packed bf16 planes
        int e = t >> 5, q = t & 31;
        float4 v = ((const float4*)g_ea)[(size_t)(base + e) * 32 + q];
        uint32_t h0, l0, h1, l1;
        split2(v.x, v.y, h0, l0);
        split2(v.z, v.w, h1, l1);
        *(uint2*)&eHi[e * 68 + 2 * q] = make_uint2(h0, h1);
        *(uint2*)&eLo[e * 68 + 2 * q] = make_uint2(l0, l1);
    }
    __syncthreads();

    int rowg = (wid >> 2) * 32;
    int cb1 = (wid & 3) * 64;
    int wcol = wid & 3;

    // GEMM1 acc init: per-fragment gather of P1[row] + P2[col]
    float4 acc[2][8];
#pragma unroll
    for (int mt = 0; mt < 2; mt++) {
        int r0 = rowg + mt * 16 + g, r1 = r0 + 8;
        const float* p1a = &g_P1[(size_t)sRow[r0] * 256];
        const float* p2a = &g_P2[(size_t)sCol[r0] * 256];
        const float* p1b = &g_P1[(size_t)sRow[r1] * 256];
        const float* p2b = &g_P2[(size_t)sCol[r1] * 256];
#pragma unroll
        for (int nt = 0; nt < 8; nt++) {
            int C = cb1 + nt * 8 + 2 * tig;
            float2 u1 = *(const float2*)&p1a[C];
            float2 u2 = *(const float2*)&p2a[C];
            float2 v1 = *(const float2*)&p1b[C];
            float2 v2 = *(const float2*)&p2b[C];
            acc[mt][nt] = make_float4(u1.x + u2.x, u1.y + u2.y,
                                      v1.x + v2.x, v1.y + v2.y);
        }
    }

    for (int kc = 0; kc < 4; kc++) {
        if (kc < 3) cp_wait1(); else cp_wait0();
        __syncthreads();
        uint32_t* wbuf = w1b + (kc & 1) * 8320;
        mma_chunk_bf<8, 2>(eHi, eLo, 68, rowg, kc * 16, wbuf, wbuf + 4160, 260, cb1, acc, lane);
        __syncthreads();
        if (kc + 2 < 4)
            issueW16x256(w1b + (kc & 1) * 8320, hi1, lo1, 128 + (kc + 2) * 16, tid);
    }

    issueW16x128(w2b, hi2, lo2, 0, tid);
    issueW16x128(w2b + 4224, hi2, lo2, 16, tid);

    // LN(256) + GELU -> t (packed, aliased over eHi/eLo region)
    {
        LN_REDUCE(8, acc, 1.0f / 256)
#pragma unroll
        for (int mt = 0; mt < 2; mt++) {
            int r0 = rowg + mt * 16 + g;
#pragma unroll
            for (int nt = 0; nt < 8; nt++) {
                int C = cb1 + nt * 8 + 2 * tig;
                int cp = C >> 1;
                float gx = sP[C], gy = sP[C + 1];
                float bx = sP[256 + C], by = sP[256 + C + 1];
                float tx = gelu((acc[mt][nt].x - m[mt][0]) * rn[mt][0] * gx + bx);
                float ty = gelu((acc[mt][nt].y - m[mt][0]) * rn[mt][0] * gy + by);
                float tz = gelu((acc[mt][nt].z - m[mt][1]) * rn[mt][1] * gx + bx);
                float tw = gelu((acc[mt][nt].w - m[mt][1]) * rn[mt][1] * gy + by);
                uint32_t h0, l0, h1, l1;
                split2(tx, ty, h0, l0);
                split2(tz, tw, h1, l1);
                tHi[r0 * 132 + cp] = h0; tLo[r0 * 132 + cp] = l0;
                tHi[(r0 + 8) * 132 + cp] = h1; tLo[(r0 + 8) * 132 + cp] = l1;
            }
        }
    }

    // GEMM2 pipelined: K=256, 8 chunks of 16 packed rows
    int cb2 = (wid & 3) * 32;
    float4 acc2[2][4];
#pragma unroll
    for (int mt = 0; mt < 2; mt++)
#pragma unroll
        for (int nt = 0; nt < 4; nt++) acc2[mt][nt] = make_float4(0, 0, 0, 0);
    for (int kc = 0; kc < 8; kc++) {
        if (kc < 7) cp_wait1(); else cp_wait0();
        __syncthreads();
        uint32_t* wbuf = w2b + (kc & 1) * 4224;
        mma_chunk_bf<4, 2>(tHi, tLo, 132, rowg, kc * 16, wbuf, wbuf + 2112, 132, cb2, acc2, lane);
        __syncthreads();
        if (kc + 2 < 8)
            issueW16x128(w2b + (kc & 1) * 4224, hi2, lo2, (kc + 2) * 16, tid);
    }

    // + b2, hoist residual loads, LN(128), residual, store + scatter
    {
#pragma unroll
        for (int mt = 0; mt < 2; mt++)
#pragma unroll
            for (int nt = 0; nt < 4; nt++) {
                int C = cb2 + nt * 8 + 2 * tig;
                acc2[mt][nt].x += sP[512 + C]; acc2[mt][nt].y += sP[512 + C + 1];
                acc2[mt][nt].z += sP[512 + C]; acc2[mt][nt].w += sP[512 + C + 1];
            }
        // hoisted residual loads (latency hidden under LN_REDUCE barrier)
        float2 eres[2][4][2];
#pragma unroll
        for (int mt = 0; mt < 2; mt++) {
            int r0 = rowg + mt * 16 + g;
            int r1 = r0 + 8;
#pragma unroll
            for (int nt = 0; nt < 4; nt++) {
                int C = cb2 + nt * 8 + 2 * tig;
                eres[mt][nt][0] = *(const float2*)&g_ea[(size_t)(base + r0) * HD + C];
                eres[mt][nt][1] = *(const float2*)&g_ea[(size_t)(base + r1) * HD + C];
            }
        }
        LN_REDUCE(4, acc2, 1.0f / 128)
#pragma unroll
        for (int mt = 0; mt < 2; mt++) {
            int r0 = rowg + mt * 16 + g;
            int r1 = r0 + 8;
#pragma unroll
            for (int nt = 0; nt < 4; nt++) {
                int C = cb2 + nt * 8 + 2 * tig;
                float gx = sP[640 + C], gy = sP[640 + C + 1];
                float bx = sP[768 + C], by = sP[768 + C + 1];
                float2 e0 = eres[mt][nt][0];
                float2 e1 = eres[mt][nt][1];
                float ox = e0.x + (acc2[mt][nt].x - m[mt][0]) * rn[mt][0] * gx + bx;
                float oy = e0.y + (acc2[mt][nt].y - m[mt][0]) * rn[mt][0] * gy + by;
                float oz = e1.x + (acc2[mt][nt].z - m[mt][1]) * rn[mt][1] * gx + bx;
                float ow = e1.y + (acc2[mt][nt].w - m[mt][1]) * rn[mt][1] * gy + by;
                *(float2*)&g_ea[(size_t)(base + r0) * HD + C] = make_float2(ox, oy);
                *(float2*)&g_ea[(size_t)(base + r1) * HD + C] = make_float2(oz, ow);
                float* a0 = &g_agg[(size_t)sCol[r0] * HD + C];
                float* a1 = &g_agg[(size_t)sCol[r1] * HD + C];
                asm volatile("red.global.add.v2.f32 [%0], {%1,%2};"
                             :: "l"(a0), "f"(ox), "f"(oy) : "memory");
                asm volatile("red.global.add.v2.f32 [%0], {%1,%2};"
                             :: "l"(a1), "f"(oz), "f"(ow) : "memory");
            }
        }
    }
}

// ---------------- fused node update (pipelined: G1 8-kp dbuf, G2 16-kp dbuf) ----------------
// smem (u32): aHi [0,8448) aLo [8448,16896)
//             G1 wbuf [16896,25216): 2 x 4160 ; G2 wbuf [16896,25344): 2 x 4224
__global__ void __launch_bounds__(256, 2) k_node(
    int w1Off, int w2Off,
    const float* __restrict__ b1, const float* __restrict__ g1,
    const float* __restrict__ bt1, const float* __restrict__ b2,
    const float* __restrict__ g2, const float* __restrict__ bt2) {
    extern __shared__ float sm[];
    uint32_t* aHi = (uint32_t*)sm;
    uint32_t* aLo = aHi + 8448;
    uint32_t* w1b = aHi + 16896;
    uint32_t* w2b = aHi + 16896;
    uint32_t* tHi = aHi;
    uint32_t* tLo = aLo;
    __shared__ __align__(16) float sRed[512];
    __shared__ float sP[1152];
    int tid = threadIdx.x, lane = tid & 31, wid = tid >> 5;
    int g = lane >> 2, tig = lane & 3;
    int base = blockIdx.x * 64;
    const uint32_t* hi1 = g_Wb + w1Off;
    const uint32_t* lo1 = hi1 + 32768;
    const uint32_t* hi2 = g_Wb + w2Off;
    const uint32_t* lo2 = hi2 + 16384;

    issueW8x256(w1b, hi1, lo1, 0, tid);
    issueW8x256(w1b + 4160, hi1, lo1, 8, tid);

    for (int t = tid; t < 1152; t += 256)
        sP[t] = (t < 256) ? b1[t] : (t < 512) ? g1[t - 256] : (t < 768) ? bt1[t - 512]
              : (t < 896) ? b2[t - 768] : (t < 1024) ? g2[t - 896] : bt2[t - 1024];

    for (int t = tid; t < 64 * 32; t += 256) {
        int i = t >> 5, q = t & 31;
        int n = base + i;
        float4 v = (n < NN) ? ((const float4*)g_h)[(size_t)n * 32 + q]
                            : make_float4(0, 0, 0, 0);
        uint32_t h0, l0, h1, l1;
        split2(v.x, v.y, h0, l0);
        split2(v.z, v.w, h1, l1);
        *(uint2*)&aHi[i * 132 + 2 * q] = make_uint2(h0, h1);
        *(uint2*)&aLo[i * 132 + 2 * q] = make_uint2(l0, l1);
    }
    for (int t = tid; t < 64 * 32; t += 256) {
        int i = t >> 5, q = t & 31;
        int n = base + i;
        float4 v = make_float4(0, 0, 0, 0);
        if (n < NN) {
            float4* ap = (float4*)&g_agg[(size_t)n * HD + q * 4];
            v = *ap;
            float iv = g_inv[n];
            v.x *= iv; v.y *= iv; v.z *= iv; v.w *= iv;
            *ap = make_float4(0, 0, 0, 0);
        }
        uint32_t h0, l0, h1, l1;
        split2(v.x, v.y, h0, l0);
        split2(v.z, v.w, h1, l1);
        *(uint2*)&aHi[i * 132 + 64 + 2 * q] = make_uint2(h0, h1);
        *(uint2*)&aLo[i * 132 + 64 + 2 * q] = make_uint2(l0, l1);
    }
    __syncthreads();

    int rowg = (wid >> 2) * 32;
    int cb1 = (wid & 3) * 64;
    int wcol = wid & 3;

    // GEMM1 (M=64, N=256, K=256): 16 pipelined chunks of 8 kp
    float4 acc[2][8];
#pragma unroll
    for (int mt = 0; mt < 2; mt++)
#pragma unroll
        for (int nt = 0; nt < 8; nt++) {
            int C = cb1 + nt * 8 + 2 * tig;
            acc[mt][nt] = make_float4(sP[C], sP[C + 1], sP[C], sP[C + 1]);
        }
    for (int kc = 0; kc < 16; kc++) {
        if (kc < 15) cp_wait1(); else cp_wait0();
        __syncthreads();
        uint32_t* wbuf = w1b + (kc & 1) * 4160;
        mma_chunk_bf<8, 1>(aHi, aLo, 132, rowg, kc * 8, wbuf, wbuf + 2080, 260, cb1, acc, lane);
        __syncthreads();
        if (kc + 2 < 16)
            issueW8x256(w1b + (kc & 1) * 4160, hi1, lo1, (kc + 2) * 8, tid);
    }

    issueW16x128(w2b, hi2, lo2, 0, tid);
    issueW16x128(w2b + 4224, hi2, lo2, 16, tid);

    // LN(256) + GELU -> t packed (aliased on A)
    {
        LN_REDUCE(8, acc, 1.0f / 256)
#pragma unroll
        for (int mt = 0; mt < 2; mt++) {
            int r0 = rowg + mt * 16 + g;
#pragma unroll
            for (int nt = 0; nt < 8; nt++) {
                int C = cb1 + nt * 8 + 2 * tig;
                int cp = C >> 1;
                float gx = sP[256 + C], gy = sP[256 + C + 1];
                float bx = sP[512 + C], by = sP[512 + C + 1];
                float tx = gelu((acc[mt][nt].x - m[mt][0]) * rn[mt][0] * gx + bx);
                float ty = gelu((acc[mt][nt].y - m[mt][0]) * rn[mt][0] * gy + by);
                float tz = gelu((acc[mt][nt].z - m[mt][1]) * rn[mt][1] * gx + bx);
                float tw = gelu((acc[mt][nt].w - m[mt][1]) * rn[mt][1] * gy + by);
                uint32_t h0, l0, h1, l1;
                split2(tx, ty, h0, l0);
                split2(tz, tw, h1, l1);
                tHi[r0 * 132 + cp] = h0; tLo[r0 * 132 + cp] = l0;
                tHi[(r0 + 8) * 132 + cp] = h1; tLo[(r0 + 8) * 132 + cp] = l1;
            }
        }
    }

    // GEMM2 (M=64, N=128, K=256): 8 pipelined chunks of 16 kp
    int cb2 = (wid & 3) * 32;
    float4 acc2[2][4];
#pragma unroll
    for (int mt = 0; mt < 2; mt++)
#pragma unroll
        for (int nt = 0; nt < 4; nt++) acc2[mt][nt] = make_float4(0, 0, 0, 0);
    for (int kc = 0; kc < 8; kc++) {
        if (kc < 7) cp_wait1(); else cp_wait0();
        __syncthreads();
        uint32_t* wbuf = w2b + (kc & 1) * 4224;
        mma_chunk_bf<4, 2>(tHi, tLo, 132, rowg, kc * 16, wbuf, wbuf + 2112, 132, cb2, acc2, lane);
        __syncthreads();
        if (kc + 2 < 8)
            issueW16x128(w2b + (kc & 1) * 4224, hi2, lo2, (kc + 2) * 16, tid);
    }

    // + b2, hoist residual loads, LN(128), residual from g_h, store h
    {
#pragma unroll
        for (int mt = 0; mt < 2; mt++)
#pragma unroll
            for (int nt = 0; nt < 4; nt++) {
                int C = cb2 + nt * 8 + 2 * tig;
                acc2[mt][nt].x += sP[768 + C]; acc2[mt][nt].y += sP[768 + C + 1];
                acc2[mt][nt].z += sP[768 + C]; acc2[mt][nt].w += sP[768 + C + 1];
            }
        // hoisted residual loads (hidden under LN_REDUCE barrier)
        float2 hres[2][4][2];
#pragma unroll
        for (int mt = 0; mt < 2; mt++) {
            int n0 = base + rowg + mt * 16 + g;
            int n1 = n0 + 8;
#pragma unroll
            for (int nt = 0; nt < 4; nt++) {
                int C = cb2 + nt * 8 + 2 * tig;
                hres[mt][nt][0] = (n0 < NN) ? *(const float2*)&g_h[(size_t)n0 * HD + C]
                                            : make_float2(0, 0);
                hres[mt][nt][1] = (n1 < NN) ? *(const float2*)&g_h[(size_t)n1 * HD + C]
                                            : make_float2(0, 0);
            }
        }
        LN_REDUCE(4, acc2, 1.0f / 128)
#pragma unroll
        for (int mt = 0; mt < 2; mt++) {
            int n0 = base + rowg + mt * 16 + g;
            int n1 = n0 + 8;
#pragma unroll
            for (int nt = 0; nt < 4; nt++) {
                int C = cb2 + nt * 8 + 2 * tig;
                float gx = sP[896 + C], gy = sP[896 + C + 1];
                float bx = sP[1024 + C], by = sP[1024 + C + 1];
                if (n0 < NN) {
                    float2 hr = hres[mt][nt][0];
                    float ox = hr.x + (acc2[mt][nt].x - m[mt][0]) * rn[mt][0] * gx + bx;
                    float oy = hr.y + (acc2[mt][nt].y - m[mt][0]) * rn[mt][0] * gy + by;
                    *(float2*)&g_h[(size_t)n0 * HD + C] = make_float2(ox, oy);
                }
                if (n1 < NN) {
                    float2 hr = hres[mt][nt][1];
                    float oz = hr.x + (acc2[mt][nt].z - m[mt][1]) * rn[mt][1] * gx + bx;
                    float ow = hr.y + (acc2[mt][nt].w - m[mt][1]) * rn[mt][1] * gy + by;
                    *(float2*)&g_h[(size_t)n1 * HD + C] = make_float2(oz, ow);
                }
            }
        }
    }
}

// ---------------- decoder ----------------
__global__ void k_dec(const float* __restrict__ W1, const float* __restrict__ b1,
                      const float* __restrict__ W2, const float* __restrict__ b2,
                      float* __restrict__ out) {
    int n = blockIdx.x, j = threadIdx.x;
    __shared__ float sh[128];
    __shared__ float st[128];
    sh[j] = g_h[(size_t)n * HD + j];
    __syncthreads();
    float a = b1[j];
#pragma unroll 8
    for (int k = 0; k < 128; k++) a = fmaf(sh[k], W1[k * HD + j], a);
    st[j] = gelu(a);
    __syncthreads();
    int w = j >> 5, lane = j & 31;
    float s = 0;
#pragma unroll
    for (int k = lane; k < 128; k += 32) s = fmaf(st[k], W2[k * 4 + w], s);
    s = warpsum(s);
    if (lane == 0) out[(size_t)n * 4 + w] = s + b2[w];
}

// ---------------- launch ----------------
extern "C" void kernel_launch(void* const* d_in, const int* in_sizes, int n_in,
                              void* d_out, int out_size) {
    (void)in_sizes; (void)n_in; (void)out_size;
    const float* x       = (const float*)d_in[0];
    const void*  ei      = d_in[1];
    const float* eattr   = (const float*)d_in[2];
    const float* enc_W   = (const float*)d_in[3];
    const float* enc_b   = (const float*)d_in[4];
    const float* enc_g   = (const float*)d_in[5];
    const float* enc_bt  = (const float*)d_in[6];
    const float* ee_W    = (const float*)d_in[7];
    const float* ee_b    = (const float*)d_in[8];
    const float* eW1     = (const float*)d_in[9];
    const float* eb1     = (const float*)d_in[10];
    const float* eg1     = (const float*)d_in[11];
    const float* ebt1    = (const float*)d_in[12];
    const float* eW2     = (const float*)d_in[13];
    const float* eb2     = (const float*)d_in[14];
    const float* eg2     = (const float*)d_in[15];
    const float* ebt2    = (const float*)d_in[16];
    const float* nW1     = (const float*)d_in[17];
    const float* nb1     = (const float*)d_in[18];
    const float* ng1     = (const float*)d_in[19];
    const float* nbt1    = (const float*)d_in[20];
    const float* nW2     = (const float*)d_in[21];
    const float* nb2     = (const float*)d_in[22];
    const float* ng2     = (const float*)d_in[23];
    const float* nbt2    = (const float*)d_in[24];
    const float* dec_W1  = (const float*)d_in[25];
    const float* dec_b1  = (const float*)d_in[26];
    const float* dec_W2  = (const float*)d_in[27];
    const float* dec_b2  = (const float*)d_in[28];

    cudaFuncSetAttribute(k_edge, cudaFuncAttributeMaxDynamicSharedMemorySize, EDGE_SMEM);
    cudaFuncSetAttribute(k_node, cudaFuncAttributeMaxDynamicSharedMemorySize, NODE_SMEM);
    cudaFuncSetAttribute(k_P,    cudaFuncAttributeMaxDynamicSharedMemorySize, P_SMEM);

    uint32_t* wb = nullptr;
    cudaGetSymbolAddress((void**)&wb, g_Wb);

    const int nodeBlocks = (NN + 63) / 64;  // 782

    // k_edge kept at my launch index 3 (harness offset +2 -> ncu -s5 captures it)
    k_prepAll<<<dim3(448, 10), 256>>>(eW1, eW2, nW1, nW2, wb);         // 0
    k_encconv<<<NN + NE + CONV_BLOCKS, 128>>>(x, enc_W, enc_b, enc_g,
        enc_bt, eattr, ee_W, ee_b, ei);                                // 1
    k_P<<<dim3(nodeBlocks, 2), 256, P_SMEM>>>(EW1_OFF, eb1);           // 2
    k_edge<<<NE / 64, 256, EDGE_SMEM>>>(EW1_OFF, EW2_OFF,
        eg1, ebt1, eb2, eg2, ebt2);                                    // 3 <- profiled
    k_inv<<<(NN + 255) / 256, 256>>>();                                // 4
    k_node<<<nodeBlocks, 256, NODE_SMEM>>>(NW1_OFF, NW2_OFF,
        nb1, ng1, nbt1, nb2, ng2, nbt2);                               // 5

    for (int l = 1; l < 10; l++) {
        k_P<<<dim3(nodeBlocks, 2), 256, P_SMEM>>>(EW1_OFF + l * 98304, eb1 + l * 256);
        k_edge<<<NE / 64, 256, EDGE_SMEM>>>(
            EW1_OFF + l * 98304, EW2_OFF + l * 32768,
            eg1 + l * 256, ebt1 + l * 256,
            eb2 + l * 128, eg2 + l * 128, ebt2 + l * 128);
        k_node<<<nodeBlocks, 256, NODE_SMEM>>>(
            NW1_OFF + l * 65536, NW2_OFF + l * 32768,
            nb1 + l * 256, ng1 + l * 256, nbt1 + l * 256,
            nb2 + l * 128, ng2 + l * 128, nbt2 + l * 128);
    }
    k_dec<<<NN, 128>>>(dec_W1, dec_b1, dec_W2, dec_b2, (float*)d_out);
}

// round 15
// speedup vs baseline: 1.1038x; 1.0200x over previous
#include <cuda_runtime.h>
#include <cuda_bf16.h>
#include <cstdint>

#define NN 50000
#define NE 600000
#define HD 128

#define EDGE_SMEM 101376   // 25344 u32
#define NODE_SMEM 101376
#define P_SMEM    101376
#define DEC_SMEM  83968    // (16384 + 512 + 2048 + 2048) * 4

// packed-weight plane offsets in g_Wb (uint32 units)
#define EW1_OFF 0          // per layer 2*192*256 = 98304
#define EW2_OFF 983040     // per layer 2*128*128 = 32768
#define NW1_OFF 1310720    // per layer 2*128*256 = 65536
#define NW2_OFF 1966080    // per layer 32768
#define WB_TOTAL 2293760

// ---------------- device scratch ----------------
__device__ float g_h[NN * HD];
__device__ float g_ea[(size_t)NE * HD];
__device__ float g_P1[(size_t)NN * 256];
__device__ float g_P2[(size_t)NN * 256];
__device__ float g_agg[NN * HD];
__device__ float g_inv[NN];
__device__ int   g_cnt[NN];
__device__ int   g_row[NE];
__device__ int   g_col[NE];
__device__ uint32_t g_Wb[WB_TOTAL];

// ---------------- helpers ----------------
__device__ __forceinline__ float gelu(float x) { return x * normcdff(x); }

__device__ __forceinline__ uint32_t pack2(float a, float b) {
    uint32_t r;
    asm("cvt.rn.bf16x2.f32 %0, %1, %2;" : "=r"(r) : "f"(b), "f"(a));
    return r;
}

__device__ __forceinline__ void split2(float a, float b, uint32_t& hi, uint32_t& lo) {
    hi = pack2(a, b);
    float ra = a - __uint_as_float(hi << 16);
    float rb = b - __uint_as_float(hi & 0xffff0000u);
    lo = pack2(ra, rb);
}

__device__ __forceinline__ void mma_bf(float4& d, const uint32_t* a,
                                       uint32_t b0, uint32_t b1) {
    asm("mma.sync.aligned.m16n8k16.row.col.f32.bf16.bf16.f32 "
        "{%0,%1,%2,%3},{%4,%5,%6,%7},{%8,%9},{%0,%1,%2,%3};"
        : "+f"(d.x), "+f"(d.y), "+f"(d.z), "+f"(d.w)
        : "r"(a[0]), "r"(a[1]), "r"(a[2]), "r"(a[3]), "r"(b0), "r"(b1));
}

__device__ __forceinline__ void cpa16(void* sdst, const void* gsrc) {
    uint32_t sa = (uint32_t)__cvta_generic_to_shared(sdst);
    asm volatile("cp.async.cg.shared.global [%0], [%1], 16;" :: "r"(sa), "l"(gsrc));
}
__device__ __forceinline__ void cp_commit() {
    asm volatile("cp.async.commit_group;" ::: "memory");
}
__device__ __forceinline__ void cp_wait1() {
    asm volatile("cp.async.wait_group 1;" ::: "memory");
}
__device__ __forceinline__ void cp_wait0() {
    asm volatile("cp.async.wait_group 0;" ::: "memory");
}

// async-stage 16 rows x 256 u32 (hi at s, lo at s+4160, ld 260)
__device__ __forceinline__ void issueW16x256(uint32_t* s,
                                             const uint32_t* __restrict__ hiP,
                                             const uint32_t* __restrict__ loP,
                                             int kpBase, int tid) {
    for (int t = tid; t < 16 * 64; t += 256) {
        int r = t >> 6, q = t & 63;
        cpa16(&s[r * 260 + q * 4], &hiP[(size_t)(kpBase + r) * 256 + q * 4]);
        cpa16(&s[4160 + r * 260 + q * 4], &loP[(size_t)(kpBase + r) * 256 + q * 4]);
    }
    cp_commit();
}

// async-stage 8 rows x 256 u32 (hi at s, lo at s+2080, ld 260)
__device__ __forceinline__ void issueW8x256(uint32_t* s,
                                            const uint32_t* __restrict__ hiP,
                                            const uint32_t* __restrict__ loP,
                                            int kpBase, int tid) {
    for (int t = tid; t < 8 * 64; t += 256) {
        int r = t >> 6, q = t & 63;
        cpa16(&s[r * 260 + q * 4], &hiP[(size_t)(kpBase + r) * 256 + q * 4]);
        cpa16(&s[2080 + r * 260 + q * 4], &loP[(size_t)(kpBase + r) * 256 + q * 4]);
    }
    cp_commit();
}

// async-stage 16 rows x 128 u32 (hi at s, lo at s+2112, ld 132)
__device__ __forceinline__ void issueW16x128(uint32_t* s,
                                             const uint32_t* __restrict__ hiP,
                                             const uint32_t* __restrict__ loP,
                                             int kpBase, int tid) {
    for (int t = tid; t < 16 * 32; t += 256) {
        int r = t >> 5, q = t & 31;
        cpa16(&s[r * 132 + q * 4], &hiP[(size_t)(kpBase + r) * 128 + q * 4]);
        cpa16(&s[2112 + r * 132 + q * 4], &loP[(size_t)(kpBase + r) * 128 + q * 4]);
    }
    cp_commit();
}

// KS k16-steps of 3-term bf16-split MMA (KS=2 -> 16 kp chunk, KS=1 -> 8 kp chunk)
template <int NT, int KS>
__device__ __forceinline__ void mma_chunk_bf(
    const uint32_t* sAh, const uint32_t* sAl, int ldA, int aRow, int kpOff,
    const uint32_t* sWh, const uint32_t* sWl, int ldW, int cb,
    float4 (&acc)[2][NT], int lane) {
    int g = lane >> 2, tig = lane & 3;
#pragma unroll
    for (int ks = 0; ks < KS; ks++) {
        int cbase = kpOff + ks * 8;
        uint32_t ah[2][4], al[2][4];
#pragma unroll
        for (int mt = 0; mt < 2; mt++) {
            int r0 = aRow + mt * 16 + g, r1 = r0 + 8;
            ah[mt][0] = sAh[r0 * ldA + cbase + tig];
            ah[mt][1] = sAh[r1 * ldA + cbase + tig];
            ah[mt][2] = sAh[r0 * ldA + cbase + tig + 4];
            ah[mt][3] = sAh[r1 * ldA + cbase + tig + 4];
            al[mt][0] = sAl[r0 * ldA + cbase + tig];
            al[mt][1] = sAl[r1 * ldA + cbase + tig];
            al[mt][2] = sAl[r0 * ldA + cbase + tig + 4];
            al[mt][3] = sAl[r1 * ldA + cbase + tig + 4];
        }
        int wr0 = ks * 8 + tig, wr1 = wr0 + 4;
#pragma unroll
        for (int nt = 0; nt < NT; nt++) {
            int n = cb + nt * 8 + g;
            uint32_t bh0 = sWh[wr0 * ldW + n], bh1 = sWh[wr1 * ldW + n];
            uint32_t bl0 = sWl[wr0 * ldW + n], bl1 = sWl[wr1 * ldW + n];
#pragma unroll
            for (int mt = 0; mt < 2; mt++) {
                mma_bf(acc[mt][nt], ah[mt], bh0, bh1);
                mma_bf(acc[mt][nt], ah[mt], bl0, bl1);
                mma_bf(acc[mt][nt], al[mt], bh0, bh1);
            }
        }
    }
}

// ---------------- fused weight pre-split (all 4 groups, one launch) ----------------
__global__ void k_prepAll(const float* __restrict__ eW1, const float* __restrict__ eW2,
                          const float* __restrict__ nW1, const float* __restrict__ nW2,
                          uint32_t* __restrict__ wb) {
    int l = blockIdx.y;
    int idx = blockIdx.x * 256 + threadIdx.x;   // < 114688
    const float* W;
    uint32_t* hp;
    int KP, N, rel;
    if (idx < 49152)      { rel = idx;          W = eW1 + (size_t)l * 98304; hp = wb + EW1_OFF + l * 98304; KP = 192; N = 256; }
    else if (idx < 65536) { rel = idx - 49152;  W = eW2 + (size_t)l * 32768; hp = wb + EW2_OFF + l * 32768; KP = 128; N = 128; }
    else if (idx < 98304) { rel = idx - 65536;  W = nW1 + (size_t)l * 65536; hp = wb + NW1_OFF + l * 65536; KP = 128; N = 256; }
    else                  { rel = idx - 98304;  W = nW2 + (size_t)l * 32768; hp = wb + NW2_OFF + l * 32768; KP = 128; N = 128; }
    int kp = rel / N, n = rel - kp * N;
    float w0 = W[(size_t)(2 * kp) * N + n];
    float w1 = W[(size_t)(2 * kp + 1) * N + n];
    uint32_t hi, lo;
    split2(w0, w1, hi, lo);
    hp[(size_t)kp * N + n] = hi;
    hp[(size_t)KP * N + (size_t)kp * N + n] = lo;
}

// ---------------- fused encoders + edge-index convert/deg (batched 16/block) ----------------
__device__ __forceinline__ float warpsum(float s) {
#pragma unroll
    for (int o = 16; o; o >>= 1) s += __shfl_xor_sync(0xffffffffu, s, o);
    return s;
}

#define ENC_BLOCKS ((NN + 15) / 16)
#define EE_BLOCKS  ((NE + 15) / 16)
#define CONV_BLOCKS ((NE + 127) / 128)

__global__ void k_encconv(const float* __restrict__ x, const float* __restrict__ encW,
                          const float* __restrict__ encb, const float* __restrict__ encg,
                          const float* __restrict__ encbt,
                          const float* __restrict__ eattr, const float* __restrict__ eeW,
                          const float* __restrict__ eeb,
                          const void* __restrict__ ei) {
    int j = threadIdx.x;
    if (blockIdx.x < ENC_BLOCKS) {
        // node encoder: 16 nodes per block, weight column in registers
        __shared__ float sx[16][8];
        __shared__ float rS[4][16], rQ[4][16];
        int nb = blockIdx.x * 16;
        float wcol[7];
#pragma unroll
        for (int k = 0; k < 7; k++) wcol[k] = encW[k * HD + j];
        float bj = encb[j], gj = encg[j], btj = encbt[j];
        for (int t = j; t < 112; t += 128) {
            int i = t / 7, k = t - i * 7;
            sx[i][k] = (nb + i < NN) ? x[(size_t)(nb + i) * 7 + k] : 0.f;
        }
        __syncthreads();
        float a[16];
#pragma unroll
        for (int i = 0; i < 16; i++) {
            float v = bj;
#pragma unroll
            for (int k = 0; k < 7; k++) v = fmaf(sx[i][k], wcol[k], v);
            a[i] = v;
        }
        int w = j >> 5, lane = j & 31;
#pragma unroll
        for (int i = 0; i < 16; i++) {
            float s = warpsum(a[i]);
            float q = warpsum(a[i] * a[i]);
            if (lane == 0) { rS[w][i] = s; rQ[w][i] = q; }
        }
        __syncthreads();
#pragma unroll
        for (int i = 0; i < 16; i++) {
            int n = nb + i;
            if (n >= NN) break;
            float m = (rS[0][i] + rS[1][i] + rS[2][i] + rS[3][i]) * (1.0f / HD);
            float Q = (rQ[0][i] + rQ[1][i] + rQ[2][i] + rQ[3][i]) * (1.0f / HD);
            float rn = rsqrtf(Q - m * m + 1e-5f);
            float t = (a[i] - m) * rn * gj + btj;
            g_h[(size_t)n * HD + j] = gelu(t);
        }
    } else if (blockIdx.x < ENC_BLOCKS + EE_BLOCKS) {
        // edge encoder: 16 edges per block, weight column in registers
        __shared__ float se[16][8];
        int eb = (blockIdx.x - ENC_BLOCKS) * 16;
        float wcol[8];
#pragma unroll
        for (int k = 0; k < 8; k++) wcol[k] = eeW[k * HD + j];
        float bj = eeb[j];
        {
            int i = j >> 3, k = j & 7;   // 128 threads cover 16x8 exactly
            se[i][k] = (eb + i < NE) ? eattr[(size_t)(eb + i) * 8 + k] : 0.f;
        }
        __syncthreads();
#pragma unroll
        for (int i = 0; i < 16; i++) {
            int e = eb + i;
            if (e >= NE) break;
            float v = bj;
#pragma unroll
            for (int k = 0; k < 8; k++) v = fmaf(se[i][k], wcol[k], v);
            g_ea[(size_t)e * HD + j] = v;
        }
    } else {
        // edge-index convert + degree; local int64-vs-int32 detection
        __shared__ int sOk;
        if (j == 0) sOk = 1;
        __syncthreads();
        if (j < 64) {
            long long v = ((const long long*)ei)[j];
            if (v < 0 || v >= NN) sOk = 0;
        }
        __syncthreads();
        int is64 = sOk;
        int e = (blockIdx.x - ENC_BLOCKS - EE_BLOCKS) * 128 + j;
        if (e < NE) {
            int r, c;
            if (is64) {
                const long long* p = (const long long*)ei;
                r = (int)p[e]; c = (int)p[NE + e];
            } else {
                const int* p = (const int*)ei;
                r = p[e]; c = p[NE + e];
            }
            g_row[e] = r;
            g_col[e] = c;
            atomicAdd(&g_cnt[c], 1);
        }
    }
}

__global__ void k_inv() {
    int n = blockIdx.x * blockDim.x + threadIdx.x;
    if (n < NN) {
        g_inv[n] = 1.0f / fmaxf((float)g_cnt[n], 1.0f);
        g_cnt[n] = 0;
    }
}

// ---------------- node projections P1 = h@W1a + b1, P2 = h@W1b (pipelined) ----------------
// smem (u32): hHi [0,4352) hLo [4352,8704) wbuf [8704,25344): 2 x 8320
__global__ void __launch_bounds__(256, 2) k_P(int w1Off, const float* __restrict__ b1) {
    extern __shared__ float sm[];
    uint32_t* hHi = (uint32_t*)sm;
    uint32_t* hLo = hHi + 4352;
    uint32_t* wbf = hHi + 8704;
    int tid = threadIdx.x, lane = tid & 31, wid = tid >> 5;
    int g = lane >> 2, tig = lane & 3;
    int base = blockIdx.x * 64;
    int part = blockIdx.y;
    const uint32_t* hiP = g_Wb + w1Off;
    const uint32_t* loP = hiP + 49152;
    float* out = part ? g_P2 : g_P1;

    issueW16x256(wbf, hiP, loP, part * 64, tid);
    issueW16x256(wbf + 8320, hiP, loP, part * 64 + 16, tid);

    for (int t = tid; t < 64 * 32; t += 256) {
        int i = t >> 5, q = t & 31;
        int n = base + i;
        float4 v = (n < NN) ? ((const float4*)g_h)[(size_t)n * 32 + q]
                            : make_float4(0, 0, 0, 0);
        uint32_t h0, l0, h1, l1;
        split2(v.x, v.y, h0, l0);
        split2(v.z, v.w, h1, l1);
        *(uint2*)&hHi[i * 68 + 2 * q] = make_uint2(h0, h1);
        *(uint2*)&hLo[i * 68 + 2 * q] = make_uint2(l0, l1);
    }
    __syncthreads();

    int rowg = (wid >> 2) * 32;
    int cb1 = (wid & 3) * 64;
    float4 acc[2][8];
#pragma unroll
    for (int mt = 0; mt < 2; mt++)
#pragma unroll
        for (int nt = 0; nt < 8; nt++) acc[mt][nt] = make_float4(0, 0, 0, 0);
    for (int kc = 0; kc < 4; kc++) {
        if (kc < 3) cp_wait1(); else cp_wait0();
        __syncthreads();
        uint32_t* wbuf = wbf + (kc & 1) * 8320;
        mma_chunk_bf<8, 2>(hHi, hLo, 68, rowg, kc * 16, wbuf, wbuf + 4160, 260, cb1, acc, lane);
        __syncthreads();
        if (kc + 2 < 4)
            issueW16x256(wbf + (kc & 1) * 8320, hiP, loP, part * 64 + (kc + 2) * 16, tid);
    }
#pragma unroll
    for (int mt = 0; mt < 2; mt++) {
        int r0 = base + rowg + mt * 16 + g;
#pragma unroll
        for (int nt = 0; nt < 8; nt++) {
            int C = cb1 + nt * 8 + 2 * tig;
            float bx = part ? 0.f : __ldg(&b1[C]);
            float by = part ? 0.f : __ldg(&b1[C + 1]);
            if (r0 < NN)
                *(float2*)&out[(size_t)r0 * 256 + C] =
                    make_float2(acc[mt][nt].x + bx, acc[mt][nt].y + by);
            if (r0 + 8 < NN)
                *(float2*)&out[(size_t)(r0 + 8) * 256 + C] =
                    make_float2(acc[mt][nt].z + bx, acc[mt][nt].w + by);
        }
    }
}

// single-pass LN reduction (sum + sumsq, one barrier)
#define LN_REDUCE(NTC, ACC, INVN)                                              \
    float p[2][2] = {{0, 0}, {0, 0}}, q[2][2] = {{0, 0}, {0, 0}};              \
    _Pragma("unroll")                                                          \
    for (int mt = 0; mt < 2; mt++)                                             \
        _Pragma("unroll")                                                      \
        for (int nt = 0; nt < NTC; nt++) {                                     \
            p[mt][0] += ACC[mt][nt].x + ACC[mt][nt].y;                         \
            q[mt][0] += ACC[mt][nt].x * ACC[mt][nt].x + ACC[mt][nt].y * ACC[mt][nt].y; \
            p[mt][1] += ACC[mt][nt].z + ACC[mt][nt].w;                         \
            q[mt][1] += ACC[mt][nt].z * ACC[mt][nt].z + ACC[mt][nt].w * ACC[mt][nt].w; \
        }                                                                      \
    _Pragma("unroll")                                                          \
    for (int mt = 0; mt < 2; mt++)                                             \
        _Pragma("unroll")                                                      \
        for (int h = 0; h < 2; h++) {                                          \
            p[mt][h] += __shfl_xor_sync(0xffffffffu, p[mt][h], 1);             \
            p[mt][h] += __shfl_xor_sync(0xffffffffu, p[mt][h], 2);             \
            q[mt][h] += __shfl_xor_sync(0xffffffffu, q[mt][h], 1);             \
            q[mt][h] += __shfl_xor_sync(0xffffffffu, q[mt][h], 2);             \
        }                                                                      \
    if (tig == 0)                                                              \
        _Pragma("unroll")                                                      \
        for (int mt = 0; mt < 2; mt++)                                         \
            _Pragma("unroll")                                                  \
            for (int h = 0; h < 2; h++) {                                      \
                int ri = (rowg + mt * 16 + h * 8 + g) * 4 + wcol;              \
                sRed[ri] = p[mt][h];                                           \
                sRed[256 + ri] = q[mt][h];                                     \
            }                                                                  \
    __syncthreads();                                                           \
    float m[2][2], rn[2][2];                                                   \
    _Pragma("unroll")                                                          \
    for (int mt = 0; mt < 2; mt++)                                             \
        _Pragma("unroll")                                                      \
        for (int h = 0; h < 2; h++) {                                          \
            int ri = (rowg + mt * 16 + h * 8 + g) * 4;                         \
            float4 s = *(const float4*)&sRed[ri];                              \
            float4 s2 = *(const float4*)&sRed[256 + ri];                       \
            float mm = (s.x + s.y + s.z + s.w) * (INVN);                       \
            float qq = (s2.x + s2.y + s2.z + s2.w) * (INVN);                   \
            m[mt][h] = mm;                                                     \
            rn[mt][h] = rsqrtf(qq - mm * mm + 1e-5f);                          \
        }

// ---------------- fused edge update (R11 proven, cp.async pipelined) ----------------
// smem (u32): eHi [0,4352) eLo [4352,8704) | tHi [0,8448) tLo [8448,16896)
//             G1 wbuf [8704,25344): 2 x 8320 ; G2 wbuf [16896,25344): 2 x 4224
__global__ void __launch_bounds__(256, 2) k_edge(
    int w1Off, int w2Off,
    const float* __restrict__ g1, const float* __restrict__ bt1,
    const float* __restrict__ b2, const float* __restrict__ g2,
    const float* __restrict__ bt2) {
    extern __shared__ float sm[];
    uint32_t* buf = (uint32_t*)sm;
    uint32_t* eHi = buf;
    uint32_t* eLo = buf + 4352;
    uint32_t* tHi = buf;
    uint32_t* tLo = buf + 8448;
    uint32_t* w1b = buf + 8704;
    uint32_t* w2b = buf + 16896;
    __shared__ int sRow[64], sCol[64];
    __shared__ __align__(16) float sRed[512];
    __shared__ float sP[896];
    int tid = threadIdx.x, lane = tid & 31, wid = tid >> 5;
    int g = lane >> 2, tig = lane & 3;
    int base = blockIdx.x * 64;
    const uint32_t* hi1 = g_Wb + w1Off;
    const uint32_t* lo1 = hi1 + 49152;
    const uint32_t* hi2 = g_Wb + w2Off;
    const uint32_t* lo2 = hi2 + 16384;

    issueW16x256(w1b, hi1, lo1, 128, tid);
    issueW16x256(w1b + 8320, hi1, lo1, 144, tid);

    if (tid < 64) { sRow[tid] = g_row[base + tid]; sCol[tid] = g_col[base + tid]; }
    for (int t = tid; t < 896; t += 256)
        sP[t] = (t < 256) ? g1[t] : (t < 512) ? bt1[t - 256]
              : (t < 640) ? b2[t - 512] : (t < 768) ? g2[t - 640] : bt2[t - 768];

    for (int t = tid; t < 64 * 32; t += 256) {   // ea tile -> packed bf16 planes
        int e = t >> 5, q = t & 31;
        float4 v = ((const float4*)g_ea)[(size_t)(base + e) * 32 + q];
        uint32_t h0, l0, h1, l1;
        split2(v.x, v.y, h0, l0);
        split2(v.z, v.w, h1, l1);
        *(uint2*)&eHi[e * 68 + 2 * q] = make_uint2(h0, h1);
        *(uint2*)&eLo[e * 68 + 2 * q] = make_uint2(l0, l1);
    }
    __syncthreads();

    int rowg = (wid >> 2) * 32;
    int cb1 = (wid & 3) * 64;
    int wcol = wid & 3;

    // GEMM1 acc init: per-fragment gather of P1[row] + P2[col]
    float4 acc[2][8];
#pragma unroll
    for (int mt = 0; mt < 2; mt++) {
        int r0 = rowg + mt * 16 + g, r1 = r0 + 8;
        const float* p1a = &g_P1[(size_t)sRow[r0] * 256];
        const float* p2a = &g_P2[(size_t)sCol[r0] * 256];
        const float* p1b = &g_P1[(size_t)sRow[r1] * 256];
        const float* p2b = &g_P2[(size_t)sCol[r1] * 256];
#pragma unroll
        for (int nt = 0; nt < 8; nt++) {
            int C = cb1 + nt * 8 + 2 * tig;
            float2 u1 = *(const float2*)&p1a[C];
            float2 u2 = *(const float2*)&p2a[C];
            float2 v1 = *(const float2*)&p1b[C];
            float2 v2 = *(const float2*)&p2b[C];
            acc[mt][nt] = make_float4(u1.x + u2.x, u1.y + u2.y,
                                      v1.x + v2.x, v1.y + v2.y);
        }
    }

    for (int kc = 0; kc < 4; kc++) {
        if (kc < 3) cp_wait1(); else cp_wait0();
        __syncthreads();
        uint32_t* wbuf = w1b + (kc & 1) * 8320;
        mma_chunk_bf<8, 2>(eHi, eLo, 68, rowg, kc * 16, wbuf, wbuf + 4160, 260, cb1, acc, lane);
        __syncthreads();
        if (kc + 2 < 4)
            issueW16x256(w1b + (kc & 1) * 8320, hi1, lo1, 128 + (kc + 2) * 16, tid);
    }

    issueW16x128(w2b, hi2, lo2, 0, tid);
    issueW16x128(w2b + 4224, hi2, lo2, 16, tid);

    // LN(256) + GELU -> t (packed, aliased over eHi/eLo region)
    {
        LN_REDUCE(8, acc, 1.0f / 256)
#pragma unroll
        for (int mt = 0; mt < 2; mt++) {
            int r0 = rowg + mt * 16 + g;
#pragma unroll
            for (int nt = 0; nt < 8; nt++) {
                int C = cb1 + nt * 8 + 2 * tig;
                int cp = C >> 1;
                float gx = sP[C], gy = sP[C + 1];
                float bx = sP[256 + C], by = sP[256 + C + 1];
                float tx = gelu((acc[mt][nt].x - m[mt][0]) * rn[mt][0] * gx + bx);
                float ty = gelu((acc[mt][nt].y - m[mt][0]) * rn[mt][0] * gy + by);
                float tz = gelu((acc[mt][nt].z - m[mt][1]) * rn[mt][1] * gx + bx);
                float tw = gelu((acc[mt][nt].w - m[mt][1]) * rn[mt][1] * gy + by);
                uint32_t h0, l0, h1, l1;
                split2(tx, ty, h0, l0);
                split2(tz, tw, h1, l1);
                tHi[r0 * 132 + cp] = h0; tLo[r0 * 132 + cp] = l0;
                tHi[(r0 + 8) * 132 + cp] = h1; tLo[(r0 + 8) * 132 + cp] = l1;
            }
        }
    }

    // GEMM2 pipelined: K=256, 8 chunks of 16 packed rows
    int cb2 = (wid & 3) * 32;
    float4 acc2[2][4];
#pragma unroll
    for (int mt = 0; mt < 2; mt++)
#pragma unroll
        for (int nt = 0; nt < 4; nt++) acc2[mt][nt] = make_float4(0, 0, 0, 0);
    for (int kc = 0; kc < 8; kc++) {
        if (kc < 7) cp_wait1(); else cp_wait0();
        __syncthreads();
        uint32_t* wbuf = w2b + (kc & 1) * 4224;
        mma_chunk_bf<4, 2>(tHi, tLo, 132, rowg, kc * 16, wbuf, wbuf + 2112, 132, cb2, acc2, lane);
        __syncthreads();
        if (kc + 2 < 8)
            issueW16x128(w2b + (kc & 1) * 4224, hi2, lo2, (kc + 2) * 16, tid);
    }

    // + b2, LN(128), residual (re-read g_ea), store + scatter
    {
#pragma unroll
        for (int mt = 0; mt < 2; mt++)
#pragma unroll
            for (int nt = 0; nt < 4; nt++) {
                int C = cb2 + nt * 8 + 2 * tig;
                acc2[mt][nt].x += sP[512 + C]; acc2[mt][nt].y += sP[512 + C + 1];
                acc2[mt][nt].z += sP[512 + C]; acc2[mt][nt].w += sP[512 + C + 1];
            }
        LN_REDUCE(4, acc2, 1.0f / 128)
#pragma unroll
        for (int mt = 0; mt < 2; mt++) {
            int r0 = rowg + mt * 16 + g;
            int r1 = r0 + 8;
#pragma unroll
            for (int nt = 0; nt < 4; nt++) {
                int C = cb2 + nt * 8 + 2 * tig;
                float gx = sP[640 + C], gy = sP[640 + C + 1];
                float bx = sP[768 + C], by = sP[768 + C + 1];
                float2 e0 = *(const float2*)&g_ea[(size_t)(base + r0) * HD + C];
                float2 e1 = *(const float2*)&g_ea[(size_t)(base + r1) * HD + C];
                float ox = e0.x + (acc2[mt][nt].x - m[mt][0]) * rn[mt][0] * gx + bx;
                float oy = e0.y + (acc2[mt][nt].y - m[mt][0]) * rn[mt][0] * gy + by;
                float oz = e1.x + (acc2[mt][nt].z - m[mt][1]) * rn[mt][1] * gx + bx;
                float ow = e1.y + (acc2[mt][nt].w - m[mt][1]) * rn[mt][1] * gy + by;
                *(float2*)&g_ea[(size_t)(base + r0) * HD + C] = make_float2(ox, oy);
                *(float2*)&g_ea[(size_t)(base + r1) * HD + C] = make_float2(oz, ow);
                float* a0 = &g_agg[(size_t)sCol[r0] * HD + C];
                float* a1 = &g_agg[(size_t)sCol[r1] * HD + C];
                asm volatile("red.global.add.v2.f32 [%0], {%1,%2};"
                             :: "l"(a0), "f"(ox), "f"(oy) : "memory");
                asm volatile("red.global.add.v2.f32 [%0], {%1,%2};"
                             :: "l"(a1), "f"(oz), "f"(ow) : "memory");
            }
        }
    }
}

// ---------------- fused node update (pipelined: G1 8-kp dbuf, G2 16-kp dbuf) ----------------
// smem (u32): aHi [0,8448) aLo [8448,16896)
//             G1 wbuf [16896,25216): 2 x 4160 ; G2 wbuf [16896,25344): 2 x 4224
__global__ void __launch_bounds__(256, 2) k_node(
    int w1Off, int w2Off,
    const float* __restrict__ b1, const float* __restrict__ g1,
    const float* __restrict__ bt1, const float* __restrict__ b2,
    const float* __restrict__ g2, const float* __restrict__ bt2) {
    extern __shared__ float sm[];
    uint32_t* aHi = (uint32_t*)sm;
    uint32_t* aLo = aHi + 8448;
    uint32_t* w1b = aHi + 16896;
    uint32_t* w2b = aHi + 16896;
    uint32_t* tHi = aHi;
    uint32_t* tLo = aLo;
    __shared__ __align__(16) float sRed[512];
    __shared__ float sP[1152];
    int tid = threadIdx.x, lane = tid & 31, wid = tid >> 5;
    int g = lane >> 2, tig = lane & 3;
    int base = blockIdx.x * 64;
    const uint32_t* hi1 = g_Wb + w1Off;
    const uint32_t* lo1 = hi1 + 32768;
    const uint32_t* hi2 = g_Wb + w2Off;
    const uint32_t* lo2 = hi2 + 16384;

    issueW8x256(w1b, hi1, lo1, 0, tid);
    issueW8x256(w1b + 4160, hi1, lo1, 8, tid);

    for (int t = tid; t < 1152; t += 256)
        sP[t] = (t < 256) ? b1[t] : (t < 512) ? g1[t - 256] : (t < 768) ? bt1[t - 512]
              : (t < 896) ? b2[t - 768] : (t < 1024) ? g2[t - 896] : bt2[t - 1024];

    for (int t = tid; t < 64 * 32; t += 256) {
        int i = t >> 5, q = t & 31;
        int n = base + i;
        float4 v = (n < NN) ? ((const float4*)g_h)[(size_t)n * 32 + q]
                            : make_float4(0, 0, 0, 0);
        uint32_t h0, l0, h1, l1;
        split2(v.x, v.y, h0, l0);
        split2(v.z, v.w, h1, l1);
        *(uint2*)&aHi[i * 132 + 2 * q] = make_uint2(h0, h1);
        *(uint2*)&aLo[i * 132 + 2 * q] = make_uint2(l0, l1);
    }
    for (int t = tid; t < 64 * 32; t += 256) {
        int i = t >> 5, q = t & 31;
        int n = base + i;
        float4 v = make_float4(0, 0, 0, 0);
        if (n < NN) {
            float4* ap = (float4*)&g_agg[(size_t)n * HD + q * 4];
            v = *ap;
            float iv = g_inv[n];
            v.x *= iv; v.y *= iv; v.z *= iv; v.w *= iv;
            *ap = make_float4(0, 0, 0, 0);
        }
        uint32_t h0, l0, h1, l1;
        split2(v.x, v.y, h0, l0);
        split2(v.z, v.w, h1, l1);
        *(uint2*)&aHi[i * 132 + 64 + 2 * q] = make_uint2(h0, h1);
        *(uint2*)&aLo[i * 132 + 64 + 2 * q] = make_uint2(l0, l1);
    }
    __syncthreads();

    int rowg = (wid >> 2) * 32;
    int cb1 = (wid & 3) * 64;
    int wcol = wid & 3;

    // GEMM1 (M=64, N=256, K=256): 16 pipelined chunks of 8 kp
    float4 acc[2][8];
#pragma unroll
    for (int mt = 0; mt < 2; mt++)
#pragma unroll
        for (int nt = 0; nt < 8; nt++) {
            int C = cb1 + nt * 8 + 2 * tig;
            acc[mt][nt] = make_float4(sP[C], sP[C + 1], sP[C], sP[C + 1]);
        }
    for (int kc = 0; kc < 16; kc++) {
        if (kc < 15) cp_wait1(); else cp_wait0();
        __syncthreads();
        uint32_t* wbuf = w1b + (kc & 1) * 4160;
        mma_chunk_bf<8, 1>(aHi, aLo, 132, rowg, kc * 8, wbuf, wbuf + 2080, 260, cb1, acc, lane);
        __syncthreads();
        if (kc + 2 < 16)
            issueW8x256(w1b + (kc & 1) * 4160, hi1, lo1, (kc + 2) * 8, tid);
    }

    issueW16x128(w2b, hi2, lo2, 0, tid);
    issueW16x128(w2b + 4224, hi2, lo2, 16, tid);

    // LN(256) + GELU -> t packed (aliased on A)
    {
        LN_REDUCE(8, acc, 1.0f / 256)
#pragma unroll
        for (int mt = 0; mt < 2; mt++) {
            int r0 = rowg + mt * 16 + g;
#pragma unroll
            for (int nt = 0; nt < 8; nt++) {
                int C = cb1 + nt * 8 + 2 * tig;
                int cp = C >> 1;
                float gx = sP[256 + C], gy = sP[256 + C + 1];
                float bx = sP[512 + C], by = sP[512 + C + 1];
                float tx = gelu((acc[mt][nt].x - m[mt][0]) * rn[mt][0] * gx + bx);
                float ty = gelu((acc[mt][nt].y - m[mt][0]) * rn[mt][0] * gy + by);
                float tz = gelu((acc[mt][nt].z - m[mt][1]) * rn[mt][1] * gx + bx);
                float tw = gelu((acc[mt][nt].w - m[mt][1]) * rn[mt][1] * gy + by);
                uint32_t h0, l0, h1, l1;
                split2(tx, ty, h0, l0);
                split2(tz, tw, h1, l1);
                tHi[r0 * 132 + cp] = h0; tLo[r0 * 132 + cp] = l0;
                tHi[(r0 + 8) * 132 + cp] = h1; tLo[(r0 + 8) * 132 + cp] = l1;
            }
        }
    }

    // GEMM2 (M=64, N=128, K=256): 8 pipelined chunks of 16 kp
    int cb2 = (wid & 3) * 32;
    float4 acc2[2][4];
#pragma unroll
    for (int mt = 0; mt < 2; mt++)
#pragma unroll
        for (int nt = 0; nt < 4; nt++) acc2[mt][nt] = make_float4(0, 0, 0, 0);
    for (int kc = 0; kc < 8; kc++) {
        if (kc < 7) cp_wait1(); else cp_wait0();
        __syncthreads();
        uint32_t* wbuf = w2b + (kc & 1) * 4224;
        mma_chunk_bf<4, 2>(tHi, tLo, 132, rowg, kc * 16, wbuf, wbuf + 2112, 132, cb2, acc2, lane);
        __syncthreads();
        if (kc + 2 < 8)
            issueW16x128(w2b + (kc & 1) * 4224, hi2, lo2, (kc + 2) * 16, tid);
    }

    // + b2, LN(128), residual from g_h, store h
    {
#pragma unroll
        for (int mt = 0; mt < 2; mt++)
#pragma unroll
            for (int nt = 0; nt < 4; nt++) {
                int C = cb2 + nt * 8 + 2 * tig;
                acc2[mt][nt].x += sP[768 + C]; acc2[mt][nt].y += sP[768 + C + 1];
                acc2[mt][nt].z += sP[768 + C]; acc2[mt][nt].w += sP[768 + C + 1];
            }
        LN_REDUCE(4, acc2, 1.0f / 128)
#pragma unroll
        for (int mt = 0; mt < 2; mt++) {
            int r0 = rowg + mt * 16 + g;
            int r1 = r0 + 8;
            int n0 = base + r0, n1 = base + r1;
#pragma unroll
            for (int nt = 0; nt < 4; nt++) {
                int C = cb2 + nt * 8 + 2 * tig;
                float gx = sP[896 + C], gy = sP[896 + C + 1];
                float bx = sP[1024 + C], by = sP[1024 + C + 1];
                if (n0 < NN) {
                    float2 hr = *(const float2*)&g_h[(size_t)n0 * HD + C];
                    float ox = hr.x + (acc2[mt][nt].x - m[mt][0]) * rn[mt][0] * gx + bx;
                    float oy = hr.y + (acc2[mt][nt].y - m[mt][0]) * rn[mt][0] * gy + by;
                    *(float2*)&g_h[(size_t)n0 * HD + C] = make_float2(ox, oy);
                }
                if (n1 < NN) {
                    float2 hr = *(const float2*)&g_h[(size_t)n1 * HD + C];
                    float oz = hr.x + (acc2[mt][nt].z - m[mt][1]) * rn[mt][1] * gx + bx;
                    float ow = hr.y + (acc2[mt][nt].w - m[mt][1]) * rn[mt][1] * gy + by;
                    *(float2*)&g_h[(size_t)n1 * HD + C] = make_float2(oz, ow);
                }
            }
        }
    }
}

// ---------------- decoder (batched 16 nodes/block, W1 staged in smem) ----------------
__global__ void k_dec(const float* __restrict__ W1, const float* __restrict__ b1,
                      const float* __restrict__ W2, const float* __restrict__ b2,
                      float* __restrict__ out) {
    extern __shared__ float ds[];
    float* sW1 = ds;            // 128x128
    float* sW2 = ds + 16384;    // 128x4
    float* sh  = ds + 16896;    // 16x128
    float* st  = ds + 18944;    // 16x128
    int j = threadIdx.x;
    int nb = blockIdx.x * 16;

    for (int t = j; t < 4096; t += 128)
        ((float4*)sW1)[t] = ((const float4*)W1)[t];
    if (j < 128) ((float4*)sW2)[j] = ((const float4*)W2)[j];
    for (int t = j; t < 2048; t += 128) {
        int i = t >> 7, k = t & 127;
        int n = nb + i;
        sh[t] = (n < NN) ? g_h[(size_t)n * HD + k] : 0.f;
    }
    __syncthreads();

    float b1j = b1[j];
#pragma unroll
    for (int i = 0; i < 16; i++) {
        float a = b1j;
        const float* hr = &sh[i * 128];
#pragma unroll 8
        for (int k = 0; k < 128; k++) a = fmaf(hr[k], sW1[k * 128 + j], a);
        st[i * 128 + j] = gelu(a);
    }
    __syncthreads();

    // 64 threads cover all 16 nodes x 4 outputs (i = j>>2 in [0,16))
    if (j < 64) {
        int i = j >> 2, w = j & 3;
        int n = nb + i;
        if (n < NN) {
            float s = b2[w];
            const float* tr = &st[i * 128];
#pragma unroll 8
            for (int k = 0; k < 128; k++) s = fmaf(tr[k], sW2[k * 4 + w], s);
            out[(size_t)n * 4 + w] = s;
        }
    }
}

// ---------------- launch ----------------
extern "C" void kernel_launch(void* const* d_in, const int* in_sizes, int n_in,
                              void* d_out, int out_size) {
    (void)in_sizes; (void)n_in; (void)out_size;
    const float* x       = (const float*)d_in[0];
    const void*  ei      = d_in[1];
    const float* eattr   = (const float*)d_in[2];
    const float* enc_W   = (const float*)d_in[3];
    const float* enc_b   = (const float*)d_in[4];
    const float* enc_g   = (const float*)d_in[5];
    const float* enc_bt  = (const float*)d_in[6];
    const float* ee_W    = (const float*)d_in[7];
    const float* ee_b    = (const float*)d_in[8];
    const float* eW1     = (const float*)d_in[9];
    const float* eb1     = (const float*)d_in[10];
    const float* eg1     = (const float*)d_in[11];
    const float* ebt1    = (const float*)d_in[12];
    const float* eW2     = (const float*)d_in[13];
    const float* eb2     = (const float*)d_in[14];
    const float* eg2     = (const float*)d_in[15];
    const float* ebt2    = (const float*)d_in[16];
    const float* nW1     = (const float*)d_in[17];
    const float* nb1     = (const float*)d_in[18];
    const float* ng1     = (const float*)d_in[19];
    const float* nbt1    = (const float*)d_in[20];
    const float* nW2     = (const float*)d_in[21];
    const float* nb2     = (const float*)d_in[22];
    const float* ng2     = (const float*)d_in[23];
    const float* nbt2    = (const float*)d_in[24];
    const float* dec_W1  = (const float*)d_in[25];
    const float* dec_b1  = (const float*)d_in[26];
    const float* dec_W2  = (const float*)d_in[27];
    const float* dec_b2  = (const float*)d_in[28];

    cudaFuncSetAttribute(k_edge, cudaFuncAttributeMaxDynamicSharedMemorySize, EDGE_SMEM);
    cudaFuncSetAttribute(k_node, cudaFuncAttributeMaxDynamicSharedMemorySize, NODE_SMEM);
    cudaFuncSetAttribute(k_P,    cudaFuncAttributeMaxDynamicSharedMemorySize, P_SMEM);
    cudaFuncSetAttribute(k_dec,  cudaFuncAttributeMaxDynamicSharedMemorySize, DEC_SMEM);

    uint32_t* wb = nullptr;
    cudaGetSymbolAddress((void**)&wb, g_Wb);

    const int nodeBlocks = (NN + 63) / 64;  // 782

    // k_edge kept at my launch index 3 (harness offset +2 -> ncu -s5 captures it)
    k_prepAll<<<dim3(448, 10), 256>>>(eW1, eW2, nW1, nW2, wb);         // 0
    k_encconv<<<ENC_BLOCKS + EE_BLOCKS + CONV_BLOCKS, 128>>>(
        x, enc_W, enc_b, enc_g, enc_bt, eattr, ee_W, ee_b, ei);        // 1
    k_P<<<dim3(nodeBlocks, 2), 256, P_SMEM>>>(EW1_OFF, eb1);           // 2
    k_edge<<<NE / 64, 256, EDGE_SMEM>>>(EW1_OFF, EW2_OFF,
        eg1, ebt1, eb2, eg2, ebt2);                                    // 3 <- profiled
    k_inv<<<(NN + 255) / 256, 256>>>();                                // 4
    k_node<<<nodeBlocks, 256, NODE_SMEM>>>(NW1_OFF, NW2_OFF,
        nb1, ng1, nbt1, nb2, ng2, nbt2);                               // 5

    for (int l = 1; l < 10; l++) {
        k_P<<<dim3(nodeBlocks, 2), 256, P_SMEM>>>(EW1_OFF + l * 98304, eb1 + l * 256);
        k_edge<<<NE / 64, 256, EDGE_SMEM>>>(
            EW1_OFF + l * 98304, EW2_OFF + l * 32768,
            eg1 + l * 256, ebt1 + l * 256,
            eb2 + l * 128, eg2 + l * 128, ebt2 + l * 128);
        k_node<<<nodeBlocks, 256, NODE_SMEM>>>(
            NW1_OFF + l * 65536, NW2_OFF + l * 32768,
            nb1 + l * 256, ng1 + l * 256, nbt1 + l * 256,
            nb2 + l * 128, ng2 + l * 128, nbt2 + l * 128);
    }
    k_dec<<<(NN + 15) / 16, 128, DEC_SMEM>>>(dec_W1, dec_b1, dec_W2, dec_b2,
                                             (float*)d_out);
}

// round 16
// speedup vs baseline: 1.1629x; 1.0535x over previous
#include <cuda_runtime.h>
#include <cuda_bf16.h>
#include <cstdint>

#define NN 50000
#define NE 600000
#define HD 128

#define EDGE_SMEM 101376   // 25344 u32
#define NODE_SMEM 101376
#define P_SMEM    101376
#define DEC_SMEM  83968

// packed-weight pair-plane offsets in g_Wb (uint32 units)
#define EW1_OFF 0          // per layer 2*192*256 = 98304
#define EW2_OFF 983040     // per layer 2*128*128 = 32768
#define NW1_OFF 1310720    // per layer 2*128*256 = 65536
#define NW2_OFF 1966080    // per layer 32768
#define WB_TOTAL 2293760

// ---------------- device scratch ----------------
__device__ float g_h[NN * HD];
__device__ float g_ea[(size_t)NE * HD];
__device__ float g_P1[(size_t)NN * 256];
__device__ float g_P2[(size_t)NN * 256];
__device__ float g_agg[NN * HD];
__device__ float g_inv[NN];
__device__ int   g_cnt[NN];
__device__ int   g_row[NE];
__device__ int   g_col[NE];
__device__ uint32_t g_Wb[WB_TOTAL];

// ---------------- helpers ----------------
__device__ __forceinline__ float gelu(float x) { return x * normcdff(x); }

__device__ __forceinline__ uint32_t pack2(float a, float b) {
    uint32_t r;
    asm("cvt.rn.bf16x2.f32 %0, %1, %2;" : "=r"(r) : "f"(b), "f"(a));
    return r;
}

__device__ __forceinline__ void split2(float a, float b, uint32_t& hi, uint32_t& lo) {
    hi = pack2(a, b);
    float ra = a - __uint_as_float(hi << 16);
    float rb = b - __uint_as_float(hi & 0xffff0000u);
    lo = pack2(ra, rb);
}

__device__ __forceinline__ void mma_bf(float4& d, const uint32_t* a,
                                       uint32_t b0, uint32_t b1) {
    asm("mma.sync.aligned.m16n8k16.row.col.f32.bf16.bf16.f32 "
        "{%0,%1,%2,%3},{%4,%5,%6,%7},{%8,%9},{%0,%1,%2,%3};"
        : "+f"(d.x), "+f"(d.y), "+f"(d.z), "+f"(d.w)
        : "r"(a[0]), "r"(a[1]), "r"(a[2]), "r"(a[3]), "r"(b0), "r"(b1));
}

__device__ __forceinline__ void cpa16(void* sdst, const void* gsrc) {
    uint32_t sa = (uint32_t)__cvta_generic_to_shared(sdst);
    asm volatile("cp.async.cg.shared.global [%0], [%1], 16;" :: "r"(sa), "l"(gsrc));
}
__device__ __forceinline__ void cp_commit() {
    asm volatile("cp.async.commit_group;" ::: "memory");
}
__device__ __forceinline__ void cp_wait1() {
    asm volatile("cp.async.wait_group 1;" ::: "memory");
}
__device__ __forceinline__ void cp_wait0() {
    asm volatile("cp.async.wait_group 0;" ::: "memory");
}

// Global pair layout: pair-row pr = (kp>>3)*4 + (kp&3) holds (W[8m+t], W[8m+t+4])
// as consecutive u32 (uint2). hi plane [KP/2][N*2], lo plane at +KP*N.

// async-stage 16 k-rows = 8 pair-rows x 512 u32 (hi at s, lo at s+4160, ld 520)
__device__ __forceinline__ void issueW16x256(uint32_t* s,
                                             const uint32_t* __restrict__ hiP,
                                             const uint32_t* __restrict__ loP,
                                             int kpBase, int tid) {
    for (int t = tid; t < 8 * 128; t += 256) {
        int r = t >> 7, q = t & 127;
        size_t go = (size_t)kpBase * 256 + r * 512 + q * 4;
        cpa16(&s[r * 520 + q * 4], &hiP[go]);
        cpa16(&s[4160 + r * 520 + q * 4], &loP[go]);
    }
    cp_commit();
}

// async-stage 8 k-rows = 4 pair-rows x 512 u32 (hi at s, lo at s+2080, ld 520)
__device__ __forceinline__ void issueW8x256(uint32_t* s,
                                            const uint32_t* __restrict__ hiP,
                                            const uint32_t* __restrict__ loP,
                                            int kpBase, int tid) {
    for (int t = tid; t < 4 * 128; t += 256) {
        int r = t >> 7, q = t & 127;
        size_t go = (size_t)kpBase * 256 + r * 512 + q * 4;
        cpa16(&s[r * 520 + q * 4], &hiP[go]);
        cpa16(&s[2080 + r * 520 + q * 4], &loP[go]);
    }
    cp_commit();
}

// async-stage 16 k-rows = 8 pair-rows x 256 u32 (hi at s, lo at s+2112, ld 264)
__device__ __forceinline__ void issueW16x128(uint32_t* s,
                                             const uint32_t* __restrict__ hiP,
                                             const uint32_t* __restrict__ loP,
                                             int kpBase, int tid) {
    for (int t = tid; t < 8 * 64; t += 256) {
        int r = t >> 6, q = t & 63;
        size_t go = (size_t)kpBase * 128 + r * 256 + q * 4;
        cpa16(&s[r * 264 + q * 4], &hiP[go]);
        cpa16(&s[2112 + r * 264 + q * 4], &loP[go]);
    }
    cp_commit();
}

// KS k16-steps of 3-term bf16-split MMA. B fragments via LDS.64 pair loads.
template <int NT, int KS>
__device__ __forceinline__ void mma_chunk_bf(
    const uint32_t* sAh, const uint32_t* sAl, int ldA, int aRow, int kpOff,
    const uint32_t* sWh, const uint32_t* sWl, int ldW, int cb,
    float4 (&acc)[2][NT], int lane) {
    int g = lane >> 2, tig = lane & 3;
#pragma unroll
    for (int ks = 0; ks < KS; ks++) {
        int cbase = kpOff + ks * 8;
        uint32_t ah[2][4], al[2][4];
#pragma unroll
        for (int mt = 0; mt < 2; mt++) {
            int r0 = aRow + mt * 16 + g, r1 = r0 + 8;
            ah[mt][0] = sAh[r0 * ldA + cbase + tig];
            ah[mt][1] = sAh[r1 * ldA + cbase + tig];
            ah[mt][2] = sAh[r0 * ldA + cbase + tig + 4];
            ah[mt][3] = sAh[r1 * ldA + cbase + tig + 4];
            al[mt][0] = sAl[r0 * ldA + cbase + tig];
            al[mt][1] = sAl[r1 * ldA + cbase + tig];
            al[mt][2] = sAl[r0 * ldA + cbase + tig + 4];
            al[mt][3] = sAl[r1 * ldA + cbase + tig + 4];
        }
        int pp = ks * 4 + tig;   // pair row within staged chunk
#pragma unroll
        for (int nt = 0; nt < NT; nt++) {
            int n = cb + nt * 8 + g;
            uint2 bh = *(const uint2*)&sWh[pp * ldW + n * 2];  // (W[wr0], W[wr0+4])
            uint2 bl = *(const uint2*)&sWl[pp * ldW + n * 2];
#pragma unroll
            for (int mt = 0; mt < 2; mt++) {
                mma_bf(acc[mt][nt], ah[mt], bh.x, bh.y);
                mma_bf(acc[mt][nt], ah[mt], bl.x, bl.y);
                mma_bf(acc[mt][nt], al[mt], bh.x, bh.y);
            }
        }
    }
}

// ---------------- fused weight pre-split (pair-row layout) ----------------
__global__ void k_prepAll(const float* __restrict__ eW1, const float* __restrict__ eW2,
                          const float* __restrict__ nW1, const float* __restrict__ nW2,
                          uint32_t* __restrict__ wb) {
    int l = blockIdx.y;
    int idx = blockIdx.x * 256 + threadIdx.x;   // < 114688
    const float* W;
    uint32_t* hp;
    int KP, N, rel;
    if (idx < 49152)      { rel = idx;          W = eW1 + (size_t)l * 98304; hp = wb + EW1_OFF + l * 98304; KP = 192; N = 256; }
    else if (idx < 65536) { rel = idx - 49152;  W = eW2 + (size_t)l * 32768; hp = wb + EW2_OFF + l * 32768; KP = 128; N = 128; }
    else if (idx < 98304) { rel = idx - 65536;  W = nW1 + (size_t)l * 65536; hp = wb + NW1_OFF + l * 65536; KP = 128; N = 256; }
    else                  { rel = idx - 98304;  W = nW2 + (size_t)l * 32768; hp = wb + NW2_OFF + l * 32768; KP = 128; N = 128; }
    int kp = rel / N, n = rel - kp * N;
    float w0 = W[(size_t)(2 * kp) * N + n];
    float w1 = W[(size_t)(2 * kp + 1) * N + n];
    uint32_t hi, lo;
    split2(w0, w1, hi, lo);
    int t = kp & 7;
    size_t off = ((size_t)(kp >> 3) * 4 + (t & 3)) * (N * 2) + (size_t)n * 2 + (t >> 2);
    hp[off] = hi;
    hp[(size_t)KP * N + off] = lo;
}

// ---------------- fused encoders + edge-index convert/deg (batched 16/block) ----------------
__device__ __forceinline__ float warpsum(float s) {
#pragma unroll
    for (int o = 16; o; o >>= 1) s += __shfl_xor_sync(0xffffffffu, s, o);
    return s;
}

#define ENC_BLOCKS ((NN + 15) / 16)
#define EE_BLOCKS  ((NE + 15) / 16)
#define CONV_BLOCKS ((NE + 127) / 128)

__global__ void k_encconv(const float* __restrict__ x, const float* __restrict__ encW,
                          const float* __restrict__ encb, const float* __restrict__ encg,
                          const float* __restrict__ encbt,
                          const float* __restrict__ eattr, const float* __restrict__ eeW,
                          const float* __restrict__ eeb,
                          const void* __restrict__ ei) {
    int j = threadIdx.x;
    if (blockIdx.x < ENC_BLOCKS) {
        __shared__ float sx[16][8];
        __shared__ float rS[4][16], rQ[4][16];
        int nb = blockIdx.x * 16;
        float wcol[7];
#pragma unroll
        for (int k = 0; k < 7; k++) wcol[k] = encW[k * HD + j];
        float bj = encb[j], gj = encg[j], btj = encbt[j];
        for (int t = j; t < 112; t += 128) {
            int i = t / 7, k = t - i * 7;
            sx[i][k] = (nb + i < NN) ? x[(size_t)(nb + i) * 7 + k] : 0.f;
        }
        __syncthreads();
        float a[16];
#pragma unroll
        for (int i = 0; i < 16; i++) {
            float v = bj;
#pragma unroll
            for (int k = 0; k < 7; k++) v = fmaf(sx[i][k], wcol[k], v);
            a[i] = v;
        }
        int w = j >> 5, lane = j & 31;
#pragma unroll
        for (int i = 0; i < 16; i++) {
            float s = warpsum(a[i]);
            float q = warpsum(a[i] * a[i]);
            if (lane == 0) { rS[w][i] = s; rQ[w][i] = q; }
        }
        __syncthreads();
#pragma unroll
        for (int i = 0; i < 16; i++) {
            int n = nb + i;
            if (n >= NN) break;
            float m = (rS[0][i] + rS[1][i] + rS[2][i] + rS[3][i]) * (1.0f / HD);
            float Q = (rQ[0][i] + rQ[1][i] + rQ[2][i] + rQ[3][i]) * (1.0f / HD);
            float rn = rsqrtf(Q - m * m + 1e-5f);
            float t = (a[i] - m) * rn * gj + btj;
            g_h[(size_t)n * HD + j] = gelu(t);
        }
    } else if (blockIdx.x < ENC_BLOCKS + EE_BLOCKS) {
        __shared__ float se[16][8];
        int eb = (blockIdx.x - ENC_BLOCKS) * 16;
        float wcol[8];
#pragma unroll
        for (int k = 0; k < 8; k++) wcol[k] = eeW[k * HD + j];
        float bj = eeb[j];
        {
            int i = j >> 3, k = j & 7;
            se[i][k] = (eb + i < NE) ? eattr[(size_t)(eb + i) * 8 + k] : 0.f;
        }
        __syncthreads();
#pragma unroll
        for (int i = 0; i < 16; i++) {
            int e = eb + i;
            if (e >= NE) break;
            float v = bj;
#pragma unroll
            for (int k = 0; k < 8; k++) v = fmaf(se[i][k], wcol[k], v);
            g_ea[(size_t)e * HD + j] = v;
        }
    } else {
        __shared__ int sOk;
        if (j == 0) sOk = 1;
        __syncthreads();
        if (j < 64) {
            long long v = ((const long long*)ei)[j];
            if (v < 0 || v >= NN) sOk = 0;
        }
        __syncthreads();
        int is64 = sOk;
        int e = (blockIdx.x - ENC_BLOCKS - EE_BLOCKS) * 128 + j;
        if (e < NE) {
            int r, c;
            if (is64) {
                const long long* p = (const long long*)ei;
                r = (int)p[e]; c = (int)p[NE + e];
            } else {
                const int* p = (const int*)ei;
                r = p[e]; c = p[NE + e];
            }
            g_row[e] = r;
            g_col[e] = c;
            atomicAdd(&g_cnt[c], 1);
        }
    }
}

__global__ void k_inv() {
    int n = blockIdx.x * blockDim.x + threadIdx.x;
    if (n < NN) {
        g_inv[n] = 1.0f / fmaxf((float)g_cnt[n], 1.0f);
        g_cnt[n] = 0;
    }
}

// ---------------- node projections P1 = h@W1a + b1, P2 = h@W1b (pipelined) ----------------
// smem (u32): hHi [0,4352) hLo [4352,8704) wbuf [8704,25344): 2 x 8320
__global__ void __launch_bounds__(256, 2) k_P(int w1Off, const float* __restrict__ b1) {
    extern __shared__ float sm[];
    uint32_t* hHi = (uint32_t*)sm;
    uint32_t* hLo = hHi + 4352;
    uint32_t* wbf = hHi + 8704;
    int tid = threadIdx.x, lane = tid & 31, wid = tid >> 5;
    int g = lane >> 2, tig = lane & 3;
    int base = blockIdx.x * 64;
    int part = blockIdx.y;
    const uint32_t* hiP = g_Wb + w1Off;
    const uint32_t* loP = hiP + 49152;
    float* out = part ? g_P2 : g_P1;

    issueW16x256(wbf, hiP, loP, part * 64, tid);
    issueW16x256(wbf + 8320, hiP, loP, part * 64 + 16, tid);

    for (int t = tid; t < 64 * 32; t += 256) {
        int i = t >> 5, q = t & 31;
        int n = base + i;
        float4 v = (n < NN) ? ((const float4*)g_h)[(size_t)n * 32 + q]
                            : make_float4(0, 0, 0, 0);
        uint32_t h0, l0, h1, l1;
        split2(v.x, v.y, h0, l0);
        split2(v.z, v.w, h1, l1);
        *(uint2*)&hHi[i * 68 + 2 * q] = make_uint2(h0, h1);
        *(uint2*)&hLo[i * 68 + 2 * q] = make_uint2(l0, l1);
    }
    __syncthreads();

    int rowg = (wid >> 2) * 32;
    int cb1 = (wid & 3) * 64;
    float4 acc[2][8];
#pragma unroll
    for (int mt = 0; mt < 2; mt++)
#pragma unroll
        for (int nt = 0; nt < 8; nt++) acc[mt][nt] = make_float4(0, 0, 0, 0);
    for (int kc = 0; kc < 4; kc++) {
        if (kc < 3) cp_wait1(); else cp_wait0();
        __syncthreads();
        uint32_t* wbuf = wbf + (kc & 1) * 8320;
        mma_chunk_bf<8, 2>(hHi, hLo, 68, rowg, kc * 16, wbuf, wbuf + 4160, 520, cb1, acc, lane);
        __syncthreads();
        if (kc + 2 < 4)
            issueW16x256(wbf + (kc & 1) * 8320, hiP, loP, part * 64 + (kc + 2) * 16, tid);
    }
#pragma unroll
    for (int mt = 0; mt < 2; mt++) {
        int r0 = base + rowg + mt * 16 + g;
#pragma unroll
        for (int nt = 0; nt < 8; nt++) {
            int C = cb1 + nt * 8 + 2 * tig;
            float bx = part ? 0.f : __ldg(&b1[C]);
            float by = part ? 0.f : __ldg(&b1[C + 1]);
            if (r0 < NN)
                *(float2*)&out[(size_t)r0 * 256 + C] =
                    make_float2(acc[mt][nt].x + bx, acc[mt][nt].y + by);
            if (r0 + 8 < NN)
                *(float2*)&out[(size_t)(r0 + 8) * 256 + C] =
                    make_float2(acc[mt][nt].z + bx, acc[mt][nt].w + by);
        }
    }
}

// single-pass LN reduction (sum + sumsq, one barrier)
#define LN_REDUCE(NTC, ACC, INVN)                                              \
    float p[2][2] = {{0, 0}, {0, 0}}, q[2][2] = {{0, 0}, {0, 0}};              \
    _Pragma("unroll")                                                          \
    for (int mt = 0; mt < 2; mt++)                                             \
        _Pragma("unroll")                                                      \
        for (int nt = 0; nt < NTC; nt++) {                                     \
            p[mt][0] += ACC[mt][nt].x + ACC[mt][nt].y;                         \
            q[mt][0] += ACC[mt][nt].x * ACC[mt][nt].x + ACC[mt][nt].y * ACC[mt][nt].y; \
            p[mt][1] += ACC[mt][nt].z + ACC[mt][nt].w;                         \
            q[mt][1] += ACC[mt][nt].z * ACC[mt][nt].z + ACC[mt][nt].w * ACC[mt][nt].w; \
        }                                                                      \
    _Pragma("unroll")                                                          \
    for (int mt = 0; mt < 2; mt++)                                             \
        _Pragma("unroll")                                                      \
        for (int h = 0; h < 2; h++) {                                          \
            p[mt][h] += __shfl_xor_sync(0xffffffffu, p[mt][h], 1);             \
            p[mt][h] += __shfl_xor_sync(0xffffffffu, p[mt][h], 2);             \
            q[mt][h] += __shfl_xor_sync(0xffffffffu, q[mt][h], 1);             \
            q[mt][h] += __shfl_xor_sync(0xffffffffu, q[mt][h], 2);             \
        }                                                                      \
    if (tig == 0)                                                              \
        _Pragma("unroll")                                                      \
        for (int mt = 0; mt < 2; mt++)                                         \
            _Pragma("unroll")                                                  \
            for (int h = 0; h < 2; h++) {                                      \
                int ri = (rowg + mt * 16 + h * 8 + g) * 4 + wcol;              \
                sRed[ri] = p[mt][h];                                           \
                sRed[256 + ri] = q[mt][h];                                     \
            }                                                                  \
    __syncthreads();                                                           \
    float m[2][2], rn[2][2];                                                   \
    _Pragma("unroll")                                                          \
    for (int mt = 0; mt < 2; mt++)                                             \
        _Pragma("unroll")                                                      \
        for (int h = 0; h < 2; h++) {                                          \
            int ri = (rowg + mt * 16 + h * 8 + g) * 4;                         \
            float4 s = *(const float4*)&sRed[ri];                              \
            float4 s2 = *(const float4*)&sRed[256 + ri];                       \
            float mm = (s.x + s.y + s.z + s.w) * (INVN);                       \
            float qq = (s2.x + s2.y + s2.z + s2.w) * (INVN);                   \
            m[mt][h] = mm;                                                     \
            rn[mt][h] = rsqrtf(qq - mm * mm + 1e-5f);                          \
        }

// ---------------- fused edge update (cp.async pipelined, paired B) ----------------
// smem (u32): eHi [0,4352) eLo [4352,8704) | tHi [0,8448) tLo [8448,16896)
//             G1 wbuf [8704,25344): 2 x 8320 ; G2 wbuf [16896,25344): 2 x 4224
__global__ void __launch_bounds__(256, 2) k_edge(
    int w1Off, int w2Off,
    const float* __restrict__ g1, const float* __restrict__ bt1,
    const float* __restrict__ b2, const float* __restrict__ g2,
    const float* __restrict__ bt2) {
    extern __shared__ float sm[];
    uint32_t* buf = (uint32_t*)sm;
    uint32_t* eHi = buf;
    uint32_t* eLo = buf + 4352;
    uint32_t* tHi = buf;
    uint32_t* tLo = buf + 8448;
    uint32_t* w1b = buf + 8704;
    uint32_t* w2b = buf + 16896;
    __shared__ int sRow[64], sCol[64];
    __shared__ __align__(16) float sRed[512];
    __shared__ float sP[896];
    int tid = threadIdx.x, lane = tid & 31, wid = tid >> 5;
    int g = lane >> 2, tig = lane & 3;
    int base = blockIdx.x * 64;
    const uint32_t* hi1 = g_Wb + w1Off;
    const uint32_t* lo1 = hi1 + 49152;
    const uint32_t* hi2 = g_Wb + w2Off;
    const uint32_t* lo2 = hi2 + 16384;

    issueW16x256(w1b, hi1, lo1, 128, tid);
    issueW16x256(w1b + 8320, hi1, lo1, 144, tid);

    if (tid < 64) { sRow[tid] = g_row[base + tid]; sCol[tid] = g_col[base + tid]; }
    for (int t = tid; t < 896; t += 256)
        sP[t] = (t < 256) ? g1[t] : (t < 512) ? bt1[t - 256]
              : (t < 640) ? b2[t - 512] : (t < 768) ? g2[t - 640] : bt2[t - 768];

    for (int t = tid; t < 64 * 32; t += 256) {   // ea tile -> packed bf16 planes
        int e = t >> 5, q = t & 31;
        float4 v = ((const float4*)g_ea)[(size_t)(base + e) * 32 + q];
        uint32_t h0, l0, h1, l1;
        split2(v.x, v.y, h0, l0);
        split2(v.z, v.w, h1, l1);
        *(uint2*)&eHi[e * 68 + 2 * q] = make_uint2(h0, h1);
        *(uint2*)&eLo[e * 68 + 2 * q] = make_uint2(l0, l1);
    }
    __syncthreads();

    int rowg = (wid >> 2) * 32;
    int cb1 = (wid & 3) * 64;
    int wcol = wid & 3;

    // GEMM1 acc init: per-fragment gather of P1[row] + P2[col]
    float4 acc[2][8];
#pragma unroll
    for (int mt = 0; mt < 2; mt++) {
        int r0 = rowg + mt * 16 + g, r1 = r0 + 8;
        const float* p1a = &g_P1[(size_t)sRow[r0] * 256];
        const float* p2a = &g_P2[(size_t)sCol[r0] * 256];
        const float* p1b = &g_P1[(size_t)sRow[r1] * 256];
        const float* p2b = &g_P2[(size_t)sCol[r1] * 256];
#pragma unroll
        for (int nt = 0; nt < 8; nt++) {
            int C = cb1 + nt * 8 + 2 * tig;
            float2 u1 = *(const float2*)&p1a[C];
            float2 u2 = *(const float2*)&p2a[C];
            float2 v1 = *(const float2*)&p1b[C];
            float2 v2 = *(const float2*)&p2b[C];
            acc[mt][nt] = make_float4(u1.x + u2.x, u1.y + u2.y,
                                      v1.x + v2.x, v1.y + v2.y);
        }
    }

    for (int kc = 0; kc < 4; kc++) {
        if (kc < 3) cp_wait1(); else cp_wait0();
        __syncthreads();
        uint32_t* wbuf = w1b + (kc & 1) * 8320;
        mma_chunk_bf<8, 2>(eHi, eLo, 68, rowg, kc * 16, wbuf, wbuf + 4160, 520, cb1, acc, lane);
        __syncthreads();
        if (kc + 2 < 4)
            issueW16x256(w1b + (kc & 1) * 8320, hi1, lo1, 128 + (kc + 2) * 16, tid);
    }

    issueW16x128(w2b, hi2, lo2, 0, tid);
    issueW16x128(w2b + 4224, hi2, lo2, 16, tid);

    // LN(256) + GELU -> t (packed, aliased over eHi/eLo region)
    {
        LN_REDUCE(8, acc, 1.0f / 256)
#pragma unroll
        for (int mt = 0; mt < 2; mt++) {
            int r0 = rowg + mt * 16 + g;
#pragma unroll
            for (int nt = 0; nt < 8; nt++) {
                int C = cb1 + nt * 8 + 2 * tig;
                int cp = C >> 1;
                float gx = sP[C], gy = sP[C + 1];
                float bx = sP[256 + C], by = sP[256 + C + 1];
                float tx = gelu((acc[mt][nt].x - m[mt][0]) * rn[mt][0] * gx + bx);
                float ty = gelu((acc[mt][nt].y - m[mt][0]) * rn[mt][0] * gy + by);
                float tz = gelu((acc[mt][nt].z - m[mt][1]) * rn[mt][1] * gx + bx);
                float tw = gelu((acc[mt][nt].w - m[mt][1]) * rn[mt][1] * gy + by);
                uint32_t h0, l0, h1, l1;
                split2(tx, ty, h0, l0);
                split2(tz, tw, h1, l1);
                tHi[r0 * 132 + cp] = h0; tLo[r0 * 132 + cp] = l0;
                tHi[(r0 + 8) * 132 + cp] = h1; tLo[(r0 + 8) * 132 + cp] = l1;
            }
        }
    }

    // GEMM2 pipelined: K=256, 8 chunks of 16 packed rows
    int cb2 = (wid & 3) * 32;
    float4 acc2[2][4];
#pragma unroll
    for (int mt = 0; mt < 2; mt++)
#pragma unroll
        for (int nt = 0; nt < 4; nt++) acc2[mt][nt] = make_float4(0, 0, 0, 0);
    for (int kc = 0; kc < 8; kc++) {
        if (kc < 7) cp_wait1(); else cp_wait0();
        __syncthreads();
        uint32_t* wbuf = w2b + (kc & 1) * 4224;
        mma_chunk_bf<4, 2>(tHi, tLo, 132, rowg, kc * 16, wbuf, wbuf + 2112, 264, cb2, acc2, lane);
        __syncthreads();
        if (kc + 2 < 8)
            issueW16x128(w2b + (kc & 1) * 4224, hi2, lo2, (kc + 2) * 16, tid);
    }

    // + b2, LN(128), residual (re-read g_ea), store + scatter
    {
#pragma unroll
        for (int mt = 0; mt < 2; mt++)
#pragma unroll
            for (int nt = 0; nt < 4; nt++) {
                int C = cb2 + nt * 8 + 2 * tig;
                acc2[mt][nt].x += sP[512 + C]; acc2[mt][nt].y += sP[512 + C + 1];
                acc2[mt][nt].z += sP[512 + C]; acc2[mt][nt].w += sP[512 + C + 1];
            }
        LN_REDUCE(4, acc2, 1.0f / 128)
#pragma unroll
        for (int mt = 0; mt < 2; mt++) {
            int r0 = rowg + mt * 16 + g;
            int r1 = r0 + 8;
#pragma unroll
            for (int nt = 0; nt < 4; nt++) {
                int C = cb2 + nt * 8 + 2 * tig;
                float gx = sP[640 + C], gy = sP[640 + C + 1];
                float bx = sP[768 + C], by = sP[768 + C + 1];
                float2 e0 = *(const float2*)&g_ea[(size_t)(base + r0) * HD + C];
                float2 e1 = *(const float2*)&g_ea[(size_t)(base + r1) * HD + C];
                float ox = e0.x + (acc2[mt][nt].x - m[mt][0]) * rn[mt][0] * gx + bx;
                float oy = e0.y + (acc2[mt][nt].y - m[mt][0]) * rn[mt][0] * gy + by;
                float oz = e1.x + (acc2[mt][nt].z - m[mt][1]) * rn[mt][1] * gx + bx;
                float ow = e1.y + (acc2[mt][nt].w - m[mt][1]) * rn[mt][1] * gy + by;
                *(float2*)&g_ea[(size_t)(base + r0) * HD + C] = make_float2(ox, oy);
                *(float2*)&g_ea[(size_t)(base + r1) * HD + C] = make_float2(oz, ow);
                float* a0 = &g_agg[(size_t)sCol[r0] * HD + C];
                float* a1 = &g_agg[(size_t)sCol[r1] * HD + C];
                asm volatile("red.global.add.v2.f32 [%0], {%1,%2};"
                             :: "l"(a0), "f"(ox), "f"(oy) : "memory");
                asm volatile("red.global.add.v2.f32 [%0], {%1,%2};"
                             :: "l"(a1), "f"(oz), "f"(ow) : "memory");
            }
        }
    }
}

// ---------------- fused node update (pipelined: G1 8-kp dbuf, G2 16-kp dbuf) ----------------
// smem (u32): aHi [0,8448) aLo [8448,16896)
//             G1 wbuf [16896,25216): 2 x 4160 ; G2 wbuf [16896,25344): 2 x 4224
__global__ void __launch_bounds__(256, 2) k_node(
    int w1Off, int w2Off,
    const float* __restrict__ b1, const float* __restrict__ g1,
    const float* __restrict__ bt1, const float* __restrict__ b2,
    const float* __restrict__ g2, const float* __restrict__ bt2) {
    extern __shared__ float sm[];
    uint32_t* aHi = (uint32_t*)sm;
    uint32_t* aLo = aHi + 8448;
    uint32_t* w1b = aHi + 16896;
    uint32_t* w2b = aHi + 16896;
    uint32_t* tHi = aHi;
    uint32_t* tLo = aLo;
    __shared__ __align__(16) float sRed[512];
    __shared__ float sP[1152];
    int tid = threadIdx.x, lane = tid & 31, wid = tid >> 5;
    int g = lane >> 2, tig = lane & 3;
    int base = blockIdx.x * 64;
    const uint32_t* hi1 = g_Wb + w1Off;
    const uint32_t* lo1 = hi1 + 32768;
    const uint32_t* hi2 = g_Wb + w2Off;
    const uint32_t* lo2 = hi2 + 16384;

    issueW8x256(w1b, hi1, lo1, 0, tid);
    issueW8x256(w1b + 4160, hi1, lo1, 8, tid);

    for (int t = tid; t < 1152; t += 256)
        sP[t] = (t < 256) ? b1[t] : (t < 512) ? g1[t - 256] : (t < 768) ? bt1[t - 512]
              : (t < 896) ? b2[t - 768] : (t < 1024) ? g2[t - 896] : bt2[t - 1024];

    for (int t = tid; t < 64 * 32; t += 256) {
        int i = t >> 5, q = t & 31;
        int n = base + i;
        float4 v = (n < NN) ? ((const float4*)g_h)[(size_t)n * 32 + q]
                            : make_float4(0, 0, 0, 0);
        uint32_t h0, l0, h1, l1;
        split2(v.x, v.y, h0, l0);
        split2(v.z, v.w, h1, l1);
        *(uint2*)&aHi[i * 132 + 2 * q] = make_uint2(h0, h1);
        *(uint2*)&aLo[i * 132 + 2 * q] = make_uint2(l0, l1);
    }
    for (int t = tid; t < 64 * 32; t += 256) {
        int i = t >> 5, q = t & 31;
        int n = base + i;
        float4 v = make_float4(0, 0, 0, 0);
        if (n < NN) {
            float4* ap = (float4*)&g_agg[(size_t)n * HD + q * 4];
            v = *ap;
            float iv = g_inv[n];
            v.x *= iv; v.y *= iv; v.z *= iv; v.w *= iv;
            *ap = make_float4(0, 0, 0, 0);
        }
        uint32_t h0, l0, h1, l1;
        split2(v.x, v.y, h0, l0);
        split2(v.z, v.w, h1, l1);
        *(uint2*)&aHi[i * 132 + 64 + 2 * q] = make_uint2(h0, h1);
        *(uint2*)&aLo[i * 132 + 64 + 2 * q] = make_uint2(l0, l1);
    }
    __syncthreads();

    int rowg = (wid >> 2) * 32;
    int cb1 = (wid & 3) * 64;
    int wcol = wid & 3;

    // GEMM1 (M=64, N=256, K=256): 16 pipelined chunks of 8 kp
    float4 acc[2][8];
#pragma unroll
    for (int mt = 0; mt < 2; mt++)
#pragma unroll
        for (int nt = 0; nt < 8; nt++) {
            int C = cb1 + nt * 8 + 2 * tig;
            acc[mt][nt] = make_float4(sP[C], sP[C + 1], sP[C], sP[C + 1]);
        }
    for (int kc = 0; kc < 16; kc++) {
        if (kc < 15) cp_wait1(); else cp_wait0();
        __syncthreads();
        uint32_t* wbuf = w1b + (kc & 1) * 4160;
        mma_chunk_bf<8, 1>(aHi, aLo, 132, rowg, kc * 8, wbuf, wbuf + 2080, 520, cb1, acc, lane);
        __syncthreads();
        if (kc + 2 < 16)
            issueW8x256(w1b + (kc & 1) * 4160, hi1, lo1, (kc + 2) * 8, tid);
    }

    issueW16x128(w2b, hi2, lo2, 0, tid);
    issueW16x128(w2b + 4224, hi2, lo2, 16, tid);

    // LN(256) + GELU -> t packed (aliased on A)
    {
        LN_REDUCE(8, acc, 1.0f / 256)
#pragma unroll
        for (int mt = 0; mt < 2; mt++) {
            int r0 = rowg + mt * 16 + g;
#pragma unroll
            for (int nt = 0; nt < 8; nt++) {
                int C = cb1 + nt * 8 + 2 * tig;
                int cp = C >> 1;
                float gx = sP[256 + C], gy = sP[256 + C + 1];
                float bx = sP[512 + C], by = sP[512 + C + 1];
                float tx = gelu((acc[mt][nt].x - m[mt][0]) * rn[mt][0] * gx + bx);
                float ty = gelu((acc[mt][nt].y - m[mt][0]) * rn[mt][0] * gy + by);
                float tz = gelu((acc[mt][nt].z - m[mt][1]) * rn[mt][1] * gx + bx);
                float tw = gelu((acc[mt][nt].w - m[mt][1]) * rn[mt][1] * gy + by);
                uint32_t h0, l0, h1, l1;
                split2(tx, ty, h0, l0);
                split2(tz, tw, h1, l1);
                tHi[r0 * 132 + cp] = h0; tLo[r0 * 132 + cp] = l0;
                tHi[(r0 + 8) * 132 + cp] = h1; tLo[(r0 + 8) * 132 + cp] = l1;
            }
        }
    }

    // GEMM2 (M=64, N=128, K=256): 8 pipelined chunks of 16 kp
    int cb2 = (wid & 3) * 32;
    float4 acc2[2][4];
#pragma unroll
    for (int mt = 0; mt < 2; mt++)
#pragma unroll
        for (int nt = 0; nt < 4; nt++) acc2[mt][nt] = make_float4(0, 0, 0, 0);
    for (int kc = 0; kc < 8; kc++) {
        if (kc < 7) cp_wait1(); else cp_wait0();
        __syncthreads();
        uint32_t* wbuf = w2b + (kc & 1) * 4224;
        mma_chunk_bf<4, 2>(tHi, tLo, 132, rowg, kc * 16, wbuf, wbuf + 2112, 264, cb2, acc2, lane);
        __syncthreads();
        if (kc + 2 < 8)
            issueW16x128(w2b + (kc & 1) * 4224, hi2, lo2, (kc + 2) * 16, tid);
    }

    // + b2, LN(128), residual from g_h, store h
    {
#pragma unroll
        for (int mt = 0; mt < 2; mt++)
#pragma unroll
            for (int nt = 0; nt < 4; nt++) {
                int C = cb2 + nt * 8 + 2 * tig;
                acc2[mt][nt].x += sP[768 + C]; acc2[mt][nt].y += sP[768 + C + 1];
                acc2[mt][nt].z += sP[768 + C]; acc2[mt][nt].w += sP[768 + C + 1];
            }
        LN_REDUCE(4, acc2, 1.0f / 128)
#pragma unroll
        for (int mt = 0; mt < 2; mt++) {
            int r0 = rowg + mt * 16 + g;
            int r1 = r0 + 8;
            int n0 = base + r0, n1 = base + r1;
#pragma unroll
            for (int nt = 0; nt < 4; nt++) {
                int C = cb2 + nt * 8 + 2 * tig;
                float gx = sP[896 + C], gy = sP[896 + C + 1];
                float bx = sP[1024 + C], by = sP[1024 + C + 1];
                if (n0 < NN) {
                    float2 hr = *(const float2*)&g_h[(size_t)n0 * HD + C];
                    float ox = hr.x + (acc2[mt][nt].x - m[mt][0]) * rn[mt][0] * gx + bx;
                    float oy = hr.y + (acc2[mt][nt].y - m[mt][0]) * rn[mt][0] * gy + by;
                    *(float2*)&g_h[(size_t)n0 * HD + C] = make_float2(ox, oy);
                }
                if (n1 < NN) {
                    float2 hr = *(const float2*)&g_h[(size_t)n1 * HD + C];
                    float oz = hr.x + (acc2[mt][nt].z - m[mt][1]) * rn[mt][1] * gx + bx;
                    float ow = hr.y + (acc2[mt][nt].w - m[mt][1]) * rn[mt][1] * gy + by;
                    *(float2*)&g_h[(size_t)n1 * HD + C] = make_float2(oz, ow);
                }
            }
        }
    }
}

// ---------------- decoder (batched 16 nodes/block, W1 staged in smem) ----------------
__global__ void k_dec(const float* __restrict__ W1, const float* __restrict__ b1,
                      const float* __restrict__ W2, const float* __restrict__ b2,
                      float* __restrict__ out) {
    extern __shared__ float ds[];
    float* sW1 = ds;            // 128x128
    float* sW2 = ds + 16384;    // 128x4
    float* sh  = ds + 16896;    // 16x128
    float* st  = ds + 18944;    // 16x128
    int j = threadIdx.x;
    int nb = blockIdx.x * 16;

    for (int t = j; t < 4096; t += 128)
        ((float4*)sW1)[t] = ((const float4*)W1)[t];
    if (j < 128) ((float4*)sW2)[j] = ((const float4*)W2)[j];
    for (int t = j; t < 2048; t += 128) {
        int i = t >> 7, k = t & 127;
        int n = nb + i;
        sh[t] = (n < NN) ? g_h[(size_t)n * HD + k] : 0.f;
    }
    __syncthreads();

    float b1j = b1[j];
#pragma unroll
    for (int i = 0; i < 16; i++) {
        float a = b1j;
        const float* hr = &sh[i * 128];
#pragma unroll 8
        for (int k = 0; k < 128; k++) a = fmaf(hr[k], sW1[k * 128 + j], a);
        st[i * 128 + j] = gelu(a);
    }
    __syncthreads();

    if (j < 64) {
        int i = j >> 2, w = j & 3;
        int n = nb + i;
        if (n < NN) {
            float s = b2[w];
            const float* tr = &st[i * 128];
#pragma unroll 8
            for (int k = 0; k < 128; k++) s = fmaf(tr[k], sW2[k * 4 + w], s);
            out[(size_t)n * 4 + w] = s;
        }
    }
}

// ---------------- launch ----------------
extern "C" void kernel_launch(void* const* d_in, const int* in_sizes, int n_in,
                              void* d_out, int out_size) {
    (void)in_sizes; (void)n_in; (void)out_size;
    const float* x       = (const float*)d_in[0];
    const void*  ei      = d_in[1];
    const float* eattr   = (const float*)d_in[2];
    const float* enc_W   = (const float*)d_in[3];
    const float* enc_b   = (const float*)d_in[4];
    const float* enc_g   = (const float*)d_in[5];
    const float* enc_bt  = (const float*)d_in[6];
    const float* ee_W    = (const float*)d_in[7];
    const float* ee_b    = (const float*)d_in[8];
    const float* eW1     = (const float*)d_in[9];
    const float* eb1     = (const float*)d_in[10];
    const float* eg1     = (const float*)d_in[11];
    const float* ebt1    = (const float*)d_in[12];
    const float* eW2     = (const float*)d_in[13];
    const float* eb2     = (const float*)d_in[14];
    const float* eg2     = (const float*)d_in[15];
    const float* ebt2    = (const float*)d_in[16];
    const float* nW1     = (const float*)d_in[17];
    const float* nb1     = (const float*)d_in[18];
    const float* ng1     = (const float*)d_in[19];
    const float* nbt1    = (const float*)d_in[20];
    const float* nW2     = (const float*)d_in[21];
    const float* nb2     = (const float*)d_in[22];
    const float* ng2     = (const float*)d_in[23];
    const float* nbt2    = (const float*)d_in[24];
    const float* dec_W1  = (const float*)d_in[25];
    const float* dec_b1  = (const float*)d_in[26];
    const float* dec_W2  = (const float*)d_in[27];
    const float* dec_b2  = (const float*)d_in[28];

    cudaFuncSetAttribute(k_edge, cudaFuncAttributeMaxDynamicSharedMemorySize, EDGE_SMEM);
    cudaFuncSetAttribute(k_node, cudaFuncAttributeMaxDynamicSharedMemorySize, NODE_SMEM);
    cudaFuncSetAttribute(k_P,    cudaFuncAttributeMaxDynamicSharedMemorySize, P_SMEM);
    cudaFuncSetAttribute(k_dec,  cudaFuncAttributeMaxDynamicSharedMemorySize, DEC_SMEM);

    uint32_t* wb = nullptr;
    cudaGetSymbolAddress((void**)&wb, g_Wb);

    const int nodeBlocks = (NN + 63) / 64;  // 782

    // k_edge kept at my launch index 3 (harness offset +2 -> ncu -s5 captures it)
    k_prepAll<<<dim3(448, 10), 256>>>(eW1, eW2, nW1, nW2, wb);         // 0
    k_encconv<<<ENC_BLOCKS + EE_BLOCKS + CONV_BLOCKS, 128>>>(
        x, enc_W, enc_b, enc_g, enc_bt, eattr, ee_W, ee_b, ei);        // 1
    k_P<<<dim3(nodeBlocks, 2), 256, P_SMEM>>>(EW1_OFF, eb1);           // 2
    k_edge<<<NE / 64, 256, EDGE_SMEM>>>(EW1_OFF, EW2_OFF,
        eg1, ebt1, eb2, eg2, ebt2);                                    // 3 <- profiled
    k_inv<<<(NN + 255) / 256, 256>>>();                                // 4
    k_node<<<nodeBlocks, 256, NODE_SMEM>>>(NW1_OFF, NW2_OFF,
        nb1, ng1, nbt1, nb2, ng2, nbt2);                               // 5

    for (int l = 1; l < 10; l++) {
        k_P<<<dim3(nodeBlocks, 2), 256, P_SMEM>>>(EW1_OFF + l * 98304, eb1 + l * 256);
        k_edge<<<NE / 64, 256, EDGE_SMEM>>>(
            EW1_OFF + l * 98304, EW2_OFF + l * 32768,
            eg1 + l * 256, ebt1 + l * 256,
            eb2 + l * 128, eg2 + l * 128, ebt2 + l * 128);
        k_node<<<nodeBlocks, 256, NODE_SMEM>>>(
            NW1_OFF + l * 65536, NW2_OFF + l * 32768,
            nb1 + l * 256, ng1 + l * 256, nbt1 + l * 256,
            nb2 + l * 128, ng2 + l * 128, nbt2 + l * 128);
    }
    k_dec<<<(NN + 15) / 16, 128, DEC_SMEM>>>(dec_W1, dec_b1, dec_W2, dec_b2,
                                             (float*)d_out);
}